// round 7
// baseline (speedup 1.0000x reference)
#include <cuda_runtime.h>
#include <math.h>

// ---- problem dims (fixed) ----
#define Bb   2
#define Ss   1024
#define Tt   2048          // B*S tokens
#define Hh   1024
#define NHh  16
#define HDd  64
#define Ee   8
#define Ii   2048
#define NSLOT (Tt*2)       // total (token, expert) pairs = 4096

// ---- scratch (device globals; no allocations allowed) ----
__device__ float g_xn[Tt*Hh];
__device__ float g_q [Tt*Hh];
__device__ float g_k [Tt*Hh];
__device__ float g_v [Tt*Hh];
__device__ float g_ao[Tt*Hh];    // attention output (pre-WO)
__device__ float g_h [Tt*Hh];    // residual after attention
__device__ float g_hn[Tt*Hh];    // ffn-normed
__device__ float g_act[NSLOT*Ii];  // swiglu activations per slot
__device__ float g_y  [NSLOT*Hh];  // expert outputs per slot
__device__ int   g_topi[Tt*2];
__device__ float g_topw[Tt*2];
__device__ int   g_slot[Tt*2];
__device__ int   g_tok [NSLOT];
__device__ int   g_cnt [Ee];
__device__ int   g_off [Ee];
__device__ int   g_fill[Ee];

// ---------------- elementwise / small kernels ----------------

__global__ void k_zero() {
    int i = threadIdx.x;
    if (i < Ee) { g_cnt[i] = 0; g_fill[i] = 0; }
}

// one block (256 thr) per token row; each thread one float4
__global__ void k_rmsnorm(const float* __restrict__ x, const float* __restrict__ w,
                          float* __restrict__ out) {
    int t = blockIdx.x;
    int i = threadIdx.x;
    const float4* xr = (const float4*)(x + (size_t)t * Hh);
    float4 v = xr[i];
    float ss = v.x*v.x + v.y*v.y + v.z*v.z + v.w*v.w;
    __shared__ float red[256];
    red[i] = ss; __syncthreads();
    for (int s = 128; s > 0; s >>= 1) {
        if (i < s) red[i] += red[i + s];
        __syncthreads();
    }
    float rinv = rsqrtf(red[0] * (1.0f / Hh) + 1e-6f);
    float4 wv = ((const float4*)w)[i];
    float4 o;
    o.x = v.x * rinv * wv.x; o.y = v.y * rinv * wv.y;
    o.z = v.z * rinv * wv.z; o.w = v.w * rinv * wv.w;
    ((float4*)(out + (size_t)t * Hh))[i] = o;
}

// RoPE in place on q and k (gridDim.y selects tensor)
__global__ void k_rope(const float* __restrict__ fc) {
    int idx = blockIdx.x * blockDim.x + threadIdx.x;   // pair index
    float* X = (blockIdx.y == 0) ? g_q : g_k;
    int j    = idx & 31;
    int head = (idx >> 5) & (NHh - 1);
    int t    = idx >> 9;
    if (t >= Tt) return;
    int s = t & (Ss - 1);
    float2* p = (float2*)(X + (size_t)t * Hh + head * HDd + 2 * j);
    float2 ab = *p;
    float cr = fc[s * HDd + 2 * j];
    float ci = fc[s * HDd + 2 * j + 1];
    float2 o;
    o.x = ab.x * cr - ab.y * ci;
    o.y = ab.x * ci + ab.y * cr;
    *p = o;
}

// ---------------- SGEMM core (64x64x16 tiles, 256 thr, 4x4/thr) ----------------
#define BM 64
#define BN 64
#define BK 16

// QKV: C = xn @ {wq,wk,wv} selected by blockIdx.z
__global__ void k_qkv(const float* __restrict__ wq, const float* __restrict__ wk,
                      const float* __restrict__ wv) {
    const float* Bm = (blockIdx.z == 0) ? wq : (blockIdx.z == 1) ? wk : wv;
    float* C = (blockIdx.z == 0) ? g_q : (blockIdx.z == 1) ? g_k : g_v;
    const float* A = g_xn;
    __shared__ float As[BK][BM];
    __shared__ float Bs[BK][BN];
    int tx = threadIdx.x, ty = threadIdx.y;
    int tid = ty * 16 + tx;
    int arow = tid >> 2, acol = (tid & 3) * 4;
    int brow = tid >> 4, bcol = (tid & 15) * 4;
    int rowBase = blockIdx.y * BM, colBase = blockIdx.x * BN;
    float acc[4][4] = {};
    for (int k0 = 0; k0 < Hh; k0 += BK) {
        float4 a = *(const float4*)(A + (size_t)(rowBase + arow) * Hh + k0 + acol);
        As[acol+0][arow] = a.x; As[acol+1][arow] = a.y;
        As[acol+2][arow] = a.z; As[acol+3][arow] = a.w;
        *(float4*)&Bs[brow][bcol] =
            *(const float4*)(Bm + (size_t)(k0 + brow) * Hh + colBase + bcol);
        __syncthreads();
        #pragma unroll
        for (int kk = 0; kk < BK; kk++) {
            float4 av = *(float4*)&As[kk][ty * 4];
            float4 bv = *(float4*)&Bs[kk][tx * 4];
            float ar[4] = {av.x, av.y, av.z, av.w};
            float br[4] = {bv.x, bv.y, bv.z, bv.w};
            #pragma unroll
            for (int i = 0; i < 4; i++)
                #pragma unroll
                for (int j = 0; j < 4; j++) acc[i][j] += ar[i] * br[j];
        }
        __syncthreads();
    }
    #pragma unroll
    for (int i = 0; i < 4; i++) {
        float4 o = make_float4(acc[i][0], acc[i][1], acc[i][2], acc[i][3]);
        *(float4*)(C + (size_t)(rowBase + ty * 4 + i) * Hh + colBase + tx * 4) = o;
    }
}

// WO with residual: h = x + ao @ wo
__global__ void k_wo(const float* __restrict__ wo, const float* __restrict__ x) {
    const float* A = g_ao;
    __shared__ float As[BK][BM];
    __shared__ float Bs[BK][BN];
    int tx = threadIdx.x, ty = threadIdx.y;
    int tid = ty * 16 + tx;
    int arow = tid >> 2, acol = (tid & 3) * 4;
    int brow = tid >> 4, bcol = (tid & 15) * 4;
    int rowBase = blockIdx.y * BM, colBase = blockIdx.x * BN;
    float acc[4][4] = {};
    for (int k0 = 0; k0 < Hh; k0 += BK) {
        float4 a = *(const float4*)(A + (size_t)(rowBase + arow) * Hh + k0 + acol);
        As[acol+0][arow] = a.x; As[acol+1][arow] = a.y;
        As[acol+2][arow] = a.z; As[acol+3][arow] = a.w;
        *(float4*)&Bs[brow][bcol] =
            *(const float4*)(wo + (size_t)(k0 + brow) * Hh + colBase + bcol);
        __syncthreads();
        #pragma unroll
        for (int kk = 0; kk < BK; kk++) {
            float4 av = *(float4*)&As[kk][ty * 4];
            float4 bv = *(float4*)&Bs[kk][tx * 4];
            float ar[4] = {av.x, av.y, av.z, av.w};
            float br[4] = {bv.x, bv.y, bv.z, bv.w};
            #pragma unroll
            for (int i = 0; i < 4; i++)
                #pragma unroll
                for (int j = 0; j < 4; j++) acc[i][j] += ar[i] * br[j];
        }
        __syncthreads();
    }
    #pragma unroll
    for (int i = 0; i < 4; i++) {
        size_t ro = (size_t)(rowBase + ty * 4 + i) * Hh + colBase + tx * 4;
        float4 xv = *(const float4*)(x + ro);
        float4 o = make_float4(acc[i][0] + xv.x, acc[i][1] + xv.y,
                               acc[i][2] + xv.z, acc[i][3] + xv.w);
        *(float4*)(g_h + ro) = o;
    }
}

// ---------------- attention: one warp per (b, head, query row) ----------------
__device__ __forceinline__ void attn_update(float s, float vx, float vy,
                                            float& m, float& l, float& ax, float& ay) {
    float mn = fmaxf(m, s);
    float sc = __expf(m - mn);
    float p  = __expf(s - mn);
    l  = l * sc + p;
    ax = ax * sc + p * vx;
    ay = ay * sc + p * vy;
    m  = mn;
}

__global__ void k_attn() {
    int gw   = (blockIdx.x * blockDim.x + threadIdx.x) >> 5;
    int lane = threadIdx.x & 31;
    if (gw >= Bb * NHh * Ss) return;
    int qi   = gw & (Ss - 1);
    int bh   = gw >> 10;
    int head = bh & (NHh - 1);
    int b    = bh >> 4;
    float2 qv = *(const float2*)(g_q + (size_t)(b * Ss + qi) * Hh + head * HDd + 2 * lane);
    qv.x *= 0.125f; qv.y *= 0.125f;          // 1/sqrt(64)
    const float* kb = g_k + ((size_t)b * Ss * Hh + head * HDd + 2 * lane);
    const float* vb = g_v + ((size_t)b * Ss * Hh + head * HDd + 2 * lane);
    float m = -1e30f, l = 0.f, ax = 0.f, ay = 0.f;
    int nk = qi + 1;
    int j = 0;
    for (; j + 4 <= nk; j += 4) {
        float2 k0 = *(const float2*)(kb + (size_t)(j + 0) * Hh);
        float2 k1 = *(const float2*)(kb + (size_t)(j + 1) * Hh);
        float2 k2 = *(const float2*)(kb + (size_t)(j + 2) * Hh);
        float2 k3 = *(const float2*)(kb + (size_t)(j + 3) * Hh);
        float s0 = qv.x * k0.x + qv.y * k0.y;
        float s1 = qv.x * k1.x + qv.y * k1.y;
        float s2 = qv.x * k2.x + qv.y * k2.y;
        float s3 = qv.x * k3.x + qv.y * k3.y;
        #pragma unroll
        for (int o = 16; o > 0; o >>= 1) {
            s0 += __shfl_xor_sync(0xffffffffu, s0, o);
            s1 += __shfl_xor_sync(0xffffffffu, s1, o);
            s2 += __shfl_xor_sync(0xffffffffu, s2, o);
            s3 += __shfl_xor_sync(0xffffffffu, s3, o);
        }
        float2 v0 = *(const float2*)(vb + (size_t)(j + 0) * Hh);
        float2 v1 = *(const float2*)(vb + (size_t)(j + 1) * Hh);
        float2 v2 = *(const float2*)(vb + (size_t)(j + 2) * Hh);
        float2 v3 = *(const float2*)(vb + (size_t)(j + 3) * Hh);
        attn_update(s0, v0.x, v0.y, m, l, ax, ay);
        attn_update(s1, v1.x, v1.y, m, l, ax, ay);
        attn_update(s2, v2.x, v2.y, m, l, ax, ay);
        attn_update(s3, v3.x, v3.y, m, l, ax, ay);
    }
    for (; j < nk; j++) {
        float2 kvv = *(const float2*)(kb + (size_t)j * Hh);
        float s = qv.x * kvv.x + qv.y * kvv.y;
        #pragma unroll
        for (int o = 16; o > 0; o >>= 1) s += __shfl_xor_sync(0xffffffffu, s, o);
        float2 vv = *(const float2*)(vb + (size_t)j * Hh);
        attn_update(s, vv.x, vv.y, m, l, ax, ay);
    }
    float inv = 1.f / l;
    float2 o = make_float2(ax * inv, ay * inv);
    *(float2*)(g_ao + (size_t)(b * Ss + qi) * Hh + head * HDd + 2 * lane) = o;
}

// ---------------- router: one warp per token ----------------
__global__ void k_router(const float* __restrict__ rw) {
    int t    = (blockIdx.x * blockDim.x + threadIdx.x) >> 5;
    int lane = threadIdx.x & 31;
    if (t >= Tt) return;
    const float* xr = g_hn + (size_t)t * Hh;
    float acc[Ee] = {};
    for (int hh = lane; hh < Hh; hh += 32) {
        float xv = xr[hh];
        #pragma unroll
        for (int e = 0; e < Ee; e++) acc[e] += xv * rw[hh * Ee + e];
    }
    #pragma unroll
    for (int e = 0; e < Ee; e++)
        #pragma unroll
        for (int o = 16; o > 0; o >>= 1) acc[e] += __shfl_xor_sync(0xffffffffu, acc[e], o);
    if (lane == 0) {
        float mx = acc[0];
        #pragma unroll
        for (int e = 1; e < Ee; e++) mx = fmaxf(mx, acc[e]);
        float p[Ee], s = 0.f;
        #pragma unroll
        for (int e = 0; e < Ee; e++) { p[e] = __expf(acc[e] - mx); s += p[e]; }
        float invs = 1.f / s;
        #pragma unroll
        for (int e = 0; e < Ee; e++) p[e] *= invs;
        int i1 = 0; float v1 = p[0];
        #pragma unroll
        for (int e = 1; e < Ee; e++) if (p[e] > v1) { v1 = p[e]; i1 = e; }
        int i2 = -1; float v2 = -1.f;
        #pragma unroll
        for (int e = 0; e < Ee; e++) if (e != i1 && p[e] > v2) { v2 = p[e]; i2 = e; }
        float inv = 1.f / (v1 + v2);
        g_topi[t * 2]     = i1; g_topi[t * 2 + 1] = i2;
        g_topw[t * 2]     = v1 * inv; g_topw[t * 2 + 1] = v2 * inv;
        atomicAdd(&g_cnt[i1], 1); atomicAdd(&g_cnt[i2], 1);
    }
}

__global__ void k_scan() {
    if (threadIdx.x == 0) {
        int o = 0;
        for (int e = 0; e < Ee; e++) { g_off[e] = o; o += g_cnt[e]; g_fill[e] = 0; }
    }
}

__global__ void k_fill() {
    int t = blockIdx.x * blockDim.x + threadIdx.x;
    if (t >= Tt) return;
    for (int kk = 0; kk < 2; kk++) {
        int e = g_topi[t * 2 + kk];
        int pos = atomicAdd(&g_fill[e], 1);
        int slot = g_off[e] + pos;
        g_tok[slot] = t;
        g_slot[t * 2 + kk] = slot;
    }
}

// ---------------- MoE GEMM 1: act = silu(hn@w1) * (hn@w3), gathered rows ----------------
__global__ void k_moe1(const float* __restrict__ w1, const float* __restrict__ w3) {
    int e = blockIdx.z;
    int cnt = g_cnt[e], base = g_off[e];
    int rtile = blockIdx.y * BM;
    if (rtile >= cnt) return;
    const float* B1 = w1 + (size_t)e * Hh * Ii;
    const float* B3 = w3 + (size_t)e * Hh * Ii;
    __shared__ float As[BK][BM];
    __shared__ float Bs1[BK][BN];
    __shared__ float Bs3[BK][BN];
    int tx = threadIdx.x, ty = threadIdx.y;
    int tid = ty * 16 + tx;
    int arow = tid >> 2, acol = (tid & 3) * 4;
    int brow = tid >> 4, bcol = (tid & 15) * 4;
    int colBase = blockIdx.x * BN;
    bool validA = (rtile + arow) < cnt;
    int tok = validA ? g_tok[base + rtile + arow] : g_tok[base];
    const float* Aptr = g_hn + (size_t)tok * Hh;
    float acc1[4][4] = {}, acc3[4][4] = {};
    for (int k0 = 0; k0 < Hh; k0 += BK) {
        float4 a = *(const float4*)(Aptr + k0 + acol);
        As[acol+0][arow] = a.x; As[acol+1][arow] = a.y;
        As[acol+2][arow] = a.z; As[acol+3][arow] = a.w;
        *(float4*)&Bs1[brow][bcol] =
            *(const float4*)(B1 + (size_t)(k0 + brow) * Ii + colBase + bcol);
        *(float4*)&Bs3[brow][bcol] =
            *(const float4*)(B3 + (size_t)(k0 + brow) * Ii + colBase + bcol);
        __syncthreads();
        #pragma unroll
        for (int kk = 0; kk < BK; kk++) {
            float4 av = *(float4*)&As[kk][ty * 4];
            float4 b1v = *(float4*)&Bs1[kk][tx * 4];
            float4 b3v = *(float4*)&Bs3[kk][tx * 4];
            float ar[4] = {av.x, av.y, av.z, av.w};
            float b1r[4] = {b1v.x, b1v.y, b1v.z, b1v.w};
            float b3r[4] = {b3v.x, b3v.y, b3v.z, b3v.w};
            #pragma unroll
            for (int i = 0; i < 4; i++)
                #pragma unroll
                for (int j = 0; j < 4; j++) {
                    acc1[i][j] += ar[i] * b1r[j];
                    acc3[i][j] += ar[i] * b3r[j];
                }
        }
        __syncthreads();
    }
    #pragma unroll
    for (int i = 0; i < 4; i++) {
        int rloc = rtile + ty * 4 + i;
        if (rloc >= cnt) continue;
        float4 o;
        float* op = &o.x;
        #pragma unroll
        for (int j = 0; j < 4; j++) {
            float h1 = acc1[i][j], h3 = acc3[i][j];
            op[j] = (h1 / (1.f + __expf(-h1))) * h3;
        }
        *(float4*)(g_act + (size_t)(base + rloc) * Ii + colBase + tx * 4) = o;
    }
}

// ---------------- MoE GEMM 2: y = act @ w2[e] ----------------
__global__ void k_moe2(const float* __restrict__ w2) {
    int e = blockIdx.z;
    int cnt = g_cnt[e], base = g_off[e];
    int rtile = blockIdx.y * BM;
    if (rtile >= cnt) return;
    const float* Bm = w2 + (size_t)e * Ii * Hh;
    __shared__ float As[BK][BM];
    __shared__ float Bs[BK][BN];
    int tx = threadIdx.x, ty = threadIdx.y;
    int tid = ty * 16 + tx;
    int arow = tid >> 2, acol = (tid & 3) * 4;
    int brow = tid >> 4, bcol = (tid & 15) * 4;
    int colBase = blockIdx.x * BN;
    bool validA = (rtile + arow) < cnt;
    int rowIdx = validA ? (base + rtile + arow) : base;
    const float* Aptr = g_act + (size_t)rowIdx * Ii;
    float acc[4][4] = {};
    for (int k0 = 0; k0 < Ii; k0 += BK) {
        float4 a = *(const float4*)(Aptr + k0 + acol);
        As[acol+0][arow] = a.x; As[acol+1][arow] = a.y;
        As[acol+2][arow] = a.z; As[acol+3][arow] = a.w;
        *(float4*)&Bs[brow][bcol] =
            *(const float4*)(Bm + (size_t)(k0 + brow) * Hh + colBase + bcol);
        __syncthreads();
        #pragma unroll
        for (int kk = 0; kk < BK; kk++) {
            float4 av = *(float4*)&As[kk][ty * 4];
            float4 bv = *(float4*)&Bs[kk][tx * 4];
            float ar[4] = {av.x, av.y, av.z, av.w};
            float br[4] = {bv.x, bv.y, bv.z, bv.w};
            #pragma unroll
            for (int i = 0; i < 4; i++)
                #pragma unroll
                for (int j = 0; j < 4; j++) acc[i][j] += ar[i] * br[j];
        }
        __syncthreads();
    }
    #pragma unroll
    for (int i = 0; i < 4; i++) {
        int rloc = rtile + ty * 4 + i;
        if (rloc >= cnt) continue;
        float4 o = make_float4(acc[i][0], acc[i][1], acc[i][2], acc[i][3]);
        *(float4*)(g_y + (size_t)(base + rloc) * Hh + colBase + tx * 4) = o;
    }
}

// ---------------- combine: out = h + w0*y[slot0] + w1*y[slot1] ----------------
__global__ void k_combine(float* __restrict__ out) {
    int t = blockIdx.x;
    int i = threadIdx.x;                 // 256 threads * float4 = 1024
    int s0 = g_slot[t * 2], s1 = g_slot[t * 2 + 1];
    float w0 = g_topw[t * 2], w1 = g_topw[t * 2 + 1];
    float4 hv = ((const float4*)g_h)[(size_t)t * 256 + i];
    float4 y0 = ((const float4*)g_y)[(size_t)s0 * 256 + i];
    float4 y1 = ((const float4*)g_y)[(size_t)s1 * 256 + i];
    float4 o;
    o.x = hv.x + w0 * y0.x + w1 * y1.x;
    o.y = hv.y + w0 * y0.y + w1 * y1.y;
    o.z = hv.z + w0 * y0.z + w1 * y1.z;
    o.w = hv.w + w0 * y0.w + w1 * y1.w;
    ((float4*)out)[(size_t)t * 256 + i] = o;
}

// ---------------- launch ----------------
extern "C" void kernel_launch(void* const* d_in, const int* in_sizes, int n_in,
                              void* d_out, int out_size) {
    const float* x    = (const float*)d_in[0];
    const float* anw  = (const float*)d_in[1];
    const float* fnw  = (const float*)d_in[2];
    const float* wq   = (const float*)d_in[3];
    const float* wk   = (const float*)d_in[4];
    const float* wv   = (const float*)d_in[5];
    const float* wo   = (const float*)d_in[6];
    const float* rw   = (const float*)d_in[7];
    const float* w1   = (const float*)d_in[8];
    const float* w3   = (const float*)d_in[9];
    const float* w2   = (const float*)d_in[10];
    const float* fc   = (const float*)d_in[11];
    float* out = (float*)d_out;

    float* d_xn; cudaGetSymbolAddress((void**)&d_xn, g_xn);
    float* d_h;  cudaGetSymbolAddress((void**)&d_h,  g_h);
    float* d_hn; cudaGetSymbolAddress((void**)&d_hn, g_hn);

    dim3 tb(16, 16);

    k_zero<<<1, 32>>>();
    k_rmsnorm<<<Tt, 256>>>(x, anw, d_xn);
    k_qkv<<<dim3(Hh / BN, Tt / BM, 3), tb>>>(wq, wk, wv);
    k_rope<<<dim3((Tt * NHh * 32) / 256, 2), 256>>>(fc);
    k_attn<<<(Bb * NHh * Ss) / 4, 128>>>();
    k_wo<<<dim3(Hh / BN, Tt / BM), tb>>>(wo, x);
    k_rmsnorm<<<Tt, 256>>>(d_h, fnw, d_hn);
    k_router<<<Tt / 8, 256>>>(rw);
    k_scan<<<1, 32>>>();
    k_fill<<<Tt / 256, 256>>>();
    k_moe1<<<dim3(Ii / BN, Tt / BM, Ee), tb>>>(w1, w3);
    k_moe2<<<dim3(Hh / BN, Tt / BM, Ee), tb>>>(w2);
    k_combine<<<Tt, 256>>>(out);
}

// round 8
// speedup vs baseline: 1.0007x; 1.0007x over previous
#include <cuda_runtime.h>
#include <math.h>

// ---- problem dims (fixed) ----
#define Bb   2
#define Ss   1024
#define Tt   2048          // B*S tokens
#define Hh   1024
#define NHh  16
#define HDd  64
#define Ee   8
#define Ii   2048
#define NSLOT (Tt*2)       // total (token, expert) pairs = 4096

// ---- scratch (device globals; no allocations allowed) ----
__device__ float g_xn[Tt*Hh];
__device__ float g_q [Tt*Hh];
__device__ float g_k [Tt*Hh];
__device__ float g_v [Tt*Hh];
__device__ float g_ao[Tt*Hh];    // attention output (pre-WO)
__device__ float g_h [Tt*Hh];    // residual after attention
__device__ float g_hn[Tt*Hh];    // ffn-normed
__device__ float g_act[NSLOT*Ii];  // swiglu activations per slot
__device__ float g_y  [NSLOT*Hh];  // expert outputs per slot
__device__ int   g_topi[Tt*2];
__device__ float g_topw[Tt*2];
__device__ int   g_slot[Tt*2];
__device__ int   g_tok [NSLOT];
__device__ int   g_cnt [Ee];
__device__ int   g_off [Ee];
__device__ int   g_fill[Ee];

// ---------------- elementwise / small kernels ----------------

__global__ void k_zero() {
    int i = threadIdx.x;
    if (i < Ee) { g_cnt[i] = 0; g_fill[i] = 0; }
}

// one block (256 thr) per token row; each thread one float4
__global__ void k_rmsnorm(const float* __restrict__ x, const float* __restrict__ w,
                          float* __restrict__ out) {
    int t = blockIdx.x;
    int i = threadIdx.x;
    const float4* xr = (const float4*)(x + (size_t)t * Hh);
    float4 v = xr[i];
    float ss = v.x*v.x + v.y*v.y + v.z*v.z + v.w*v.w;
    __shared__ float red[256];
    red[i] = ss; __syncthreads();
    for (int s = 128; s > 0; s >>= 1) {
        if (i < s) red[i] += red[i + s];
        __syncthreads();
    }
    float rinv = rsqrtf(red[0] * (1.0f / Hh) + 1e-6f);
    float4 wv = ((const float4*)w)[i];
    float4 o;
    o.x = v.x * rinv * wv.x; o.y = v.y * rinv * wv.y;
    o.z = v.z * rinv * wv.z; o.w = v.w * rinv * wv.w;
    ((float4*)(out + (size_t)t * Hh))[i] = o;
}

// RoPE in place on q and k (gridDim.y selects tensor)
__global__ void k_rope(const float* __restrict__ fc) {
    int idx = blockIdx.x * blockDim.x + threadIdx.x;   // pair index
    float* X = (blockIdx.y == 0) ? g_q : g_k;
    int j    = idx & 31;
    int head = (idx >> 5) & (NHh - 1);
    int t    = idx >> 9;
    if (t >= Tt) return;
    int s = t & (Ss - 1);
    float2* p = (float2*)(X + (size_t)t * Hh + head * HDd + 2 * j);
    float2 ab = *p;
    float cr = fc[s * HDd + 2 * j];
    float ci = fc[s * HDd + 2 * j + 1];
    float2 o;
    o.x = ab.x * cr - ab.y * ci;
    o.y = ab.x * ci + ab.y * cr;
    *p = o;
}

// ---------------- SGEMM core (64x64x16 tiles, 256 thr, 4x4/thr) ----------------
#define BM 64
#define BN 64
#define BK 16

// QKV: C = xn @ {wq,wk,wv} selected by blockIdx.z
__global__ void k_qkv(const float* __restrict__ wq, const float* __restrict__ wk,
                      const float* __restrict__ wv) {
    const float* Bm = (blockIdx.z == 0) ? wq : (blockIdx.z == 1) ? wk : wv;
    float* C = (blockIdx.z == 0) ? g_q : (blockIdx.z == 1) ? g_k : g_v;
    const float* A = g_xn;
    __shared__ float As[BK][BM];
    __shared__ float Bs[BK][BN];
    int tx = threadIdx.x, ty = threadIdx.y;
    int tid = ty * 16 + tx;
    int arow = tid >> 2, acol = (tid & 3) * 4;
    int brow = tid >> 4, bcol = (tid & 15) * 4;
    int rowBase = blockIdx.y * BM, colBase = blockIdx.x * BN;
    float acc[4][4] = {};
    for (int k0 = 0; k0 < Hh; k0 += BK) {
        float4 a = *(const float4*)(A + (size_t)(rowBase + arow) * Hh + k0 + acol);
        As[acol+0][arow] = a.x; As[acol+1][arow] = a.y;
        As[acol+2][arow] = a.z; As[acol+3][arow] = a.w;
        *(float4*)&Bs[brow][bcol] =
            *(const float4*)(Bm + (size_t)(k0 + brow) * Hh + colBase + bcol);
        __syncthreads();
        #pragma unroll
        for (int kk = 0; kk < BK; kk++) {
            float4 av = *(float4*)&As[kk][ty * 4];
            float4 bv = *(float4*)&Bs[kk][tx * 4];
            float ar[4] = {av.x, av.y, av.z, av.w};
            float br[4] = {bv.x, bv.y, bv.z, bv.w};
            #pragma unroll
            for (int i = 0; i < 4; i++)
                #pragma unroll
                for (int j = 0; j < 4; j++) acc[i][j] += ar[i] * br[j];
        }
        __syncthreads();
    }
    #pragma unroll
    for (int i = 0; i < 4; i++) {
        float4 o = make_float4(acc[i][0], acc[i][1], acc[i][2], acc[i][3]);
        *(float4*)(C + (size_t)(rowBase + ty * 4 + i) * Hh + colBase + tx * 4) = o;
    }
}

// WO with residual: h = x + ao @ wo
__global__ void k_wo(const float* __restrict__ wo, const float* __restrict__ x) {
    const float* A = g_ao;
    __shared__ float As[BK][BM];
    __shared__ float Bs[BK][BN];
    int tx = threadIdx.x, ty = threadIdx.y;
    int tid = ty * 16 + tx;
    int arow = tid >> 2, acol = (tid & 3) * 4;
    int brow = tid >> 4, bcol = (tid & 15) * 4;
    int rowBase = blockIdx.y * BM, colBase = blockIdx.x * BN;
    float acc[4][4] = {};
    for (int k0 = 0; k0 < Hh; k0 += BK) {
        float4 a = *(const float4*)(A + (size_t)(rowBase + arow) * Hh + k0 + acol);
        As[acol+0][arow] = a.x; As[acol+1][arow] = a.y;
        As[acol+2][arow] = a.z; As[acol+3][arow] = a.w;
        *(float4*)&Bs[brow][bcol] =
            *(const float4*)(wo + (size_t)(k0 + brow) * Hh + colBase + bcol);
        __syncthreads();
        #pragma unroll
        for (int kk = 0; kk < BK; kk++) {
            float4 av = *(float4*)&As[kk][ty * 4];
            float4 bv = *(float4*)&Bs[kk][tx * 4];
            float ar[4] = {av.x, av.y, av.z, av.w};
            float br[4] = {bv.x, bv.y, bv.z, bv.w};
            #pragma unroll
            for (int i = 0; i < 4; i++)
                #pragma unroll
                for (int j = 0; j < 4; j++) acc[i][j] += ar[i] * br[j];
        }
        __syncthreads();
    }
    #pragma unroll
    for (int i = 0; i < 4; i++) {
        size_t ro = (size_t)(rowBase + ty * 4 + i) * Hh + colBase + tx * 4;
        float4 xv = *(const float4*)(x + ro);
        float4 o = make_float4(acc[i][0] + xv.x, acc[i][1] + xv.y,
                               acc[i][2] + xv.z, acc[i][3] + xv.w);
        *(float4*)(g_h + ro) = o;
    }
}

// ---------------- attention: one warp per (b, head, query row) ----------------
__device__ __forceinline__ void attn_update(float s, float vx, float vy,
                                            float& m, float& l, float& ax, float& ay) {
    float mn = fmaxf(m, s);
    float sc = __expf(m - mn);
    float p  = __expf(s - mn);
    l  = l * sc + p;
    ax = ax * sc + p * vx;
    ay = ay * sc + p * vy;
    m  = mn;
}

__global__ void k_attn() {
    int gw   = (blockIdx.x * blockDim.x + threadIdx.x) >> 5;
    int lane = threadIdx.x & 31;
    if (gw >= Bb * NHh * Ss) return;
    int qi   = gw & (Ss - 1);
    int bh   = gw >> 10;
    int head = bh & (NHh - 1);
    int b    = bh >> 4;
    float2 qv = *(const float2*)(g_q + (size_t)(b * Ss + qi) * Hh + head * HDd + 2 * lane);
    qv.x *= 0.125f; qv.y *= 0.125f;          // 1/sqrt(64)
    const float* kb = g_k + ((size_t)b * Ss * Hh + head * HDd + 2 * lane);
    const float* vb = g_v + ((size_t)b * Ss * Hh + head * HDd + 2 * lane);
    float m = -1e30f, l = 0.f, ax = 0.f, ay = 0.f;
    int nk = qi + 1;
    int j = 0;
    for (; j + 4 <= nk; j += 4) {
        float2 k0 = *(const float2*)(kb + (size_t)(j + 0) * Hh);
        float2 k1 = *(const float2*)(kb + (size_t)(j + 1) * Hh);
        float2 k2 = *(const float2*)(kb + (size_t)(j + 2) * Hh);
        float2 k3 = *(const float2*)(kb + (size_t)(j + 3) * Hh);
        float s0 = qv.x * k0.x + qv.y * k0.y;
        float s1 = qv.x * k1.x + qv.y * k1.y;
        float s2 = qv.x * k2.x + qv.y * k2.y;
        float s3 = qv.x * k3.x + qv.y * k3.y;
        #pragma unroll
        for (int o = 16; o > 0; o >>= 1) {
            s0 += __shfl_xor_sync(0xffffffffu, s0, o);
            s1 += __shfl_xor_sync(0xffffffffu, s1, o);
            s2 += __shfl_xor_sync(0xffffffffu, s2, o);
            s3 += __shfl_xor_sync(0xffffffffu, s3, o);
        }
        float2 v0 = *(const float2*)(vb + (size_t)(j + 0) * Hh);
        float2 v1 = *(const float2*)(vb + (size_t)(j + 1) * Hh);
        float2 v2 = *(const float2*)(vb + (size_t)(j + 2) * Hh);
        float2 v3 = *(const float2*)(vb + (size_t)(j + 3) * Hh);
        attn_update(s0, v0.x, v0.y, m, l, ax, ay);
        attn_update(s1, v1.x, v1.y, m, l, ax, ay);
        attn_update(s2, v2.x, v2.y, m, l, ax, ay);
        attn_update(s3, v3.x, v3.y, m, l, ax, ay);
    }
    for (; j < nk; j++) {
        float2 kvv = *(const float2*)(kb + (size_t)j * Hh);
        float s = qv.x * kvv.x + qv.y * kvv.y;
        #pragma unroll
        for (int o = 16; o > 0; o >>= 1) s += __shfl_xor_sync(0xffffffffu, s, o);
        float2 vv = *(const float2*)(vb + (size_t)j * Hh);
        attn_update(s, vv.x, vv.y, m, l, ax, ay);
    }
    float inv = 1.f / l;
    float2 o = make_float2(ax * inv, ay * inv);
    *(float2*)(g_ao + (size_t)(b * Ss + qi) * Hh + head * HDd + 2 * lane) = o;
}

// ---------------- router: one warp per token ----------------
__global__ void k_router(const float* __restrict__ rw) {
    int t    = (blockIdx.x * blockDim.x + threadIdx.x) >> 5;
    int lane = threadIdx.x & 31;
    if (t >= Tt) return;
    const float* xr = g_hn + (size_t)t * Hh;
    float acc[Ee] = {};
    for (int hh = lane; hh < Hh; hh += 32) {
        float xv = xr[hh];
        #pragma unroll
        for (int e = 0; e < Ee; e++) acc[e] += xv * rw[hh * Ee + e];
    }
    #pragma unroll
    for (int e = 0; e < Ee; e++)
        #pragma unroll
        for (int o = 16; o > 0; o >>= 1) acc[e] += __shfl_xor_sync(0xffffffffu, acc[e], o);
    if (lane == 0) {
        float mx = acc[0];
        #pragma unroll
        for (int e = 1; e < Ee; e++) mx = fmaxf(mx, acc[e]);
        float p[Ee], s = 0.f;
        #pragma unroll
        for (int e = 0; e < Ee; e++) { p[e] = __expf(acc[e] - mx); s += p[e]; }
        float invs = 1.f / s;
        #pragma unroll
        for (int e = 0; e < Ee; e++) p[e] *= invs;
        int i1 = 0; float v1 = p[0];
        #pragma unroll
        for (int e = 1; e < Ee; e++) if (p[e] > v1) { v1 = p[e]; i1 = e; }
        int i2 = -1; float v2 = -1.f;
        #pragma unroll
        for (int e = 0; e < Ee; e++) if (e != i1 && p[e] > v2) { v2 = p[e]; i2 = e; }
        float inv = 1.f / (v1 + v2);
        g_topi[t * 2]     = i1; g_topi[t * 2 + 1] = i2;
        g_topw[t * 2]     = v1 * inv; g_topw[t * 2 + 1] = v2 * inv;
        atomicAdd(&g_cnt[i1], 1); atomicAdd(&g_cnt[i2], 1);
    }
}

__global__ void k_scan() {
    if (threadIdx.x == 0) {
        int o = 0;
        for (int e = 0; e < Ee; e++) { g_off[e] = o; o += g_cnt[e]; g_fill[e] = 0; }
    }
}

__global__ void k_fill() {
    int t = blockIdx.x * blockDim.x + threadIdx.x;
    if (t >= Tt) return;
    for (int kk = 0; kk < 2; kk++) {
        int e = g_topi[t * 2 + kk];
        int pos = atomicAdd(&g_fill[e], 1);
        int slot = g_off[e] + pos;
        g_tok[slot] = t;
        g_slot[t * 2 + kk] = slot;
    }
}

// ---------------- MoE GEMM 1: act = silu(hn@w1) * (hn@w3), gathered rows ----------------
__global__ void k_moe1(const float* __restrict__ w1, const float* __restrict__ w3) {
    int e = blockIdx.z;
    int cnt = g_cnt[e], base = g_off[e];
    int rtile = blockIdx.y * BM;
    if (rtile >= cnt) return;
    const float* B1 = w1 + (size_t)e * Hh * Ii;
    const float* B3 = w3 + (size_t)e * Hh * Ii;
    __shared__ float As[BK][BM];
    __shared__ float Bs1[BK][BN];
    __shared__ float Bs3[BK][BN];
    int tx = threadIdx.x, ty = threadIdx.y;
    int tid = ty * 16 + tx;
    int arow = tid >> 2, acol = (tid & 3) * 4;
    int brow = tid >> 4, bcol = (tid & 15) * 4;
    int colBase = blockIdx.x * BN;
    bool validA = (rtile + arow) < cnt;
    int tok = validA ? g_tok[base + rtile + arow] : g_tok[base];
    const float* Aptr = g_hn + (size_t)tok * Hh;
    float acc1[4][4] = {}, acc3[4][4] = {};
    for (int k0 = 0; k0 < Hh; k0 += BK) {
        float4 a = *(const float4*)(Aptr + k0 + acol);
        As[acol+0][arow] = a.x; As[acol+1][arow] = a.y;
        As[acol+2][arow] = a.z; As[acol+3][arow] = a.w;
        *(float4*)&Bs1[brow][bcol] =
            *(const float4*)(B1 + (size_t)(k0 + brow) * Ii + colBase + bcol);
        *(float4*)&Bs3[brow][bcol] =
            *(const float4*)(B3 + (size_t)(k0 + brow) * Ii + colBase + bcol);
        __syncthreads();
        #pragma unroll
        for (int kk = 0; kk < BK; kk++) {
            float4 av = *(float4*)&As[kk][ty * 4];
            float4 b1v = *(float4*)&Bs1[kk][tx * 4];
            float4 b3v = *(float4*)&Bs3[kk][tx * 4];
            float ar[4] = {av.x, av.y, av.z, av.w};
            float b1r[4] = {b1v.x, b1v.y, b1v.z, b1v.w};
            float b3r[4] = {b3v.x, b3v.y, b3v.z, b3v.w};
            #pragma unroll
            for (int i = 0; i < 4; i++)
                #pragma unroll
                for (int j = 0; j < 4; j++) {
                    acc1[i][j] += ar[i] * b1r[j];
                    acc3[i][j] += ar[i] * b3r[j];
                }
        }
        __syncthreads();
    }
    #pragma unroll
    for (int i = 0; i < 4; i++) {
        int rloc = rtile + ty * 4 + i;
        if (rloc >= cnt) continue;
        float4 o;
        float* op = &o.x;
        #pragma unroll
        for (int j = 0; j < 4; j++) {
            float h1 = acc1[i][j], h3 = acc3[i][j];
            op[j] = (h1 / (1.f + __expf(-h1))) * h3;
        }
        *(float4*)(g_act + (size_t)(base + rloc) * Ii + colBase + tx * 4) = o;
    }
}

// ---------------- MoE GEMM 2: y = act @ w2[e] ----------------
__global__ void k_moe2(const float* __restrict__ w2) {
    int e = blockIdx.z;
    int cnt = g_cnt[e], base = g_off[e];
    int rtile = blockIdx.y * BM;
    if (rtile >= cnt) return;
    const float* Bm = w2 + (size_t)e * Ii * Hh;
    __shared__ float As[BK][BM];
    __shared__ float Bs[BK][BN];
    int tx = threadIdx.x, ty = threadIdx.y;
    int tid = ty * 16 + tx;
    int arow = tid >> 2, acol = (tid & 3) * 4;
    int brow = tid >> 4, bcol = (tid & 15) * 4;
    int colBase = blockIdx.x * BN;
    bool validA = (rtile + arow) < cnt;
    int rowIdx = validA ? (base + rtile + arow) : base;
    const float* Aptr = g_act + (size_t)rowIdx * Ii;
    float acc[4][4] = {};
    for (int k0 = 0; k0 < Ii; k0 += BK) {
        float4 a = *(const float4*)(Aptr + k0 + acol);
        As[acol+0][arow] = a.x; As[acol+1][arow] = a.y;
        As[acol+2][arow] = a.z; As[acol+3][arow] = a.w;
        *(float4*)&Bs[brow][bcol] =
            *(const float4*)(Bm + (size_t)(k0 + brow) * Hh + colBase + bcol);
        __syncthreads();
        #pragma unroll
        for (int kk = 0; kk < BK; kk++) {
            float4 av = *(float4*)&As[kk][ty * 4];
            float4 bv = *(float4*)&Bs[kk][tx * 4];
            float ar[4] = {av.x, av.y, av.z, av.w};
            float br[4] = {bv.x, bv.y, bv.z, bv.w};
            #pragma unroll
            for (int i = 0; i < 4; i++)
                #pragma unroll
                for (int j = 0; j < 4; j++) acc[i][j] += ar[i] * br[j];
        }
        __syncthreads();
    }
    #pragma unroll
    for (int i = 0; i < 4; i++) {
        int rloc = rtile + ty * 4 + i;
        if (rloc >= cnt) continue;
        float4 o = make_float4(acc[i][0], acc[i][1], acc[i][2], acc[i][3]);
        *(float4*)(g_y + (size_t)(base + rloc) * Hh + colBase + tx * 4) = o;
    }
}

// ---------------- combine: out = h + w0*y[slot0] + w1*y[slot1] ----------------
__global__ void k_combine(float* __restrict__ out) {
    int t = blockIdx.x;
    int i = threadIdx.x;                 // 256 threads * float4 = 1024
    int s0 = g_slot[t * 2], s1 = g_slot[t * 2 + 1];
    float w0 = g_topw[t * 2], w1 = g_topw[t * 2 + 1];
    float4 hv = ((const float4*)g_h)[(size_t)t * 256 + i];
    float4 y0 = ((const float4*)g_y)[(size_t)s0 * 256 + i];
    float4 y1 = ((const float4*)g_y)[(size_t)s1 * 256 + i];
    float4 o;
    o.x = hv.x + w0 * y0.x + w1 * y1.x;
    o.y = hv.y + w0 * y0.y + w1 * y1.y;
    o.z = hv.z + w0 * y0.z + w1 * y1.z;
    o.w = hv.w + w0 * y0.w + w1 * y1.w;
    ((float4*)out)[(size_t)t * 256 + i] = o;
}

// ---------------- launch ----------------
extern "C" void kernel_launch(void* const* d_in, const int* in_sizes, int n_in,
                              void* d_out, int out_size) {
    const float* x    = (const float*)d_in[0];
    const float* anw  = (const float*)d_in[1];
    const float* fnw  = (const float*)d_in[2];
    const float* wq   = (const float*)d_in[3];
    const float* wk   = (const float*)d_in[4];
    const float* wv   = (const float*)d_in[5];
    const float* wo   = (const float*)d_in[6];
    const float* rw   = (const float*)d_in[7];
    const float* w1   = (const float*)d_in[8];
    const float* w3   = (const float*)d_in[9];
    const float* w2   = (const float*)d_in[10];
    const float* fc   = (const float*)d_in[11];
    float* out = (float*)d_out;

    float* d_xn; cudaGetSymbolAddress((void**)&d_xn, g_xn);
    float* d_h;  cudaGetSymbolAddress((void**)&d_h,  g_h);
    float* d_hn; cudaGetSymbolAddress((void**)&d_hn, g_hn);

    dim3 tb(16, 16);

    k_zero<<<1, 32>>>();
    k_rmsnorm<<<Tt, 256>>>(x, anw, d_xn);
    k_qkv<<<dim3(Hh / BN, Tt / BM, 3), tb>>>(wq, wk, wv);
    k_rope<<<dim3((Tt * NHh * 32) / 256, 2), 256>>>(fc);
    k_attn<<<(Bb * NHh * Ss) / 4, 128>>>();
    k_wo<<<dim3(Hh / BN, Tt / BM), tb>>>(wo, x);
    k_rmsnorm<<<Tt, 256>>>(d_h, fnw, d_hn);
    k_router<<<Tt / 8, 256>>>(rw);
    k_scan<<<1, 32>>>();
    k_fill<<<Tt / 256, 256>>>();
    k_moe1<<<dim3(Ii / BN, Tt / BM, Ee), tb>>>(w1, w3);
    k_moe2<<<dim3(Hh / BN, Tt / BM, Ee), tb>>>(w2);
    k_combine<<<Tt, 256>>>(out);
}

// round 9
// speedup vs baseline: 1.0047x; 1.0040x over previous
#include <cuda_runtime.h>
#include <math.h>

// ---- problem dims (fixed) ----
#define Bb   2
#define Ss   1024
#define Tt   2048          // B*S tokens
#define Hh   1024
#define NHh  16
#define HDd  64
#define Ee   8
#define Ii   2048
#define NSLOT (Tt*2)       // total (token, expert) pairs = 4096

// ---- scratch (device globals; no allocations allowed) ----
__device__ float g_xn[Tt*Hh];
__device__ float g_q [Tt*Hh];
__device__ float g_k [Tt*Hh];
__device__ float g_v [Tt*Hh];
__device__ float g_ao[Tt*Hh];    // attention output (pre-WO)
__device__ float g_h [Tt*Hh];    // residual after attention
__device__ float g_hn[Tt*Hh];    // ffn-normed
__device__ float g_act[NSLOT*Ii];  // swiglu activations per slot
__device__ float g_y  [NSLOT*Hh];  // expert outputs per slot
__device__ int   g_topi[Tt*2];
__device__ float g_topw[Tt*2];
__device__ int   g_slot[Tt*2];
__device__ int   g_tok [NSLOT];
__device__ int   g_cnt [Ee];
__device__ int   g_off [Ee];
__device__ int   g_fill[Ee];

// ---------------- elementwise / small kernels ----------------

__global__ void k_zero() {
    int i = threadIdx.x;
    if (i < Ee) { g_cnt[i] = 0; g_fill[i] = 0; }
}

// one block (256 thr) per token row; each thread one float4
__global__ void k_rmsnorm(const float* __restrict__ x, const float* __restrict__ w,
                          float* __restrict__ out) {
    int t = blockIdx.x;
    int i = threadIdx.x;
    const float4* xr = (const float4*)(x + (size_t)t * Hh);
    float4 v = xr[i];
    float ss = v.x*v.x + v.y*v.y + v.z*v.z + v.w*v.w;
    __shared__ float red[256];
    red[i] = ss; __syncthreads();
    for (int s = 128; s > 0; s >>= 1) {
        if (i < s) red[i] += red[i + s];
        __syncthreads();
    }
    float rinv = rsqrtf(red[0] * (1.0f / Hh) + 1e-6f);
    float4 wv = ((const float4*)w)[i];
    float4 o;
    o.x = v.x * rinv * wv.x; o.y = v.y * rinv * wv.y;
    o.z = v.z * rinv * wv.z; o.w = v.w * rinv * wv.w;
    ((float4*)(out + (size_t)t * Hh))[i] = o;
}

// RoPE in place on q and k (gridDim.y selects tensor)
__global__ void k_rope(const float* __restrict__ fc) {
    int idx = blockIdx.x * blockDim.x + threadIdx.x;   // pair index
    float* X = (blockIdx.y == 0) ? g_q : g_k;
    int j    = idx & 31;
    int head = (idx >> 5) & (NHh - 1);
    int t    = idx >> 9;
    if (t >= Tt) return;
    int s = t & (Ss - 1);
    float2* p = (float2*)(X + (size_t)t * Hh + head * HDd + 2 * j);
    float2 ab = *p;
    float cr = fc[s * HDd + 2 * j];
    float ci = fc[s * HDd + 2 * j + 1];
    float2 o;
    o.x = ab.x * cr - ab.y * ci;
    o.y = ab.x * ci + ab.y * cr;
    *p = o;
}

// ---------------- SGEMM core (64x64x16 tiles, 256 thr, 4x4/thr) ----------------
#define BM 64
#define BN 64
#define BK 16

// QKV: C = xn @ {wq,wk,wv} selected by blockIdx.z
__global__ void k_qkv(const float* __restrict__ wq, const float* __restrict__ wk,
                      const float* __restrict__ wv) {
    const float* Bm = (blockIdx.z == 0) ? wq : (blockIdx.z == 1) ? wk : wv;
    float* C = (blockIdx.z == 0) ? g_q : (blockIdx.z == 1) ? g_k : g_v;
    const float* A = g_xn;
    __shared__ float As[BK][BM];
    __shared__ float Bs[BK][BN];
    int tx = threadIdx.x, ty = threadIdx.y;
    int tid = ty * 16 + tx;
    int arow = tid >> 2, acol = (tid & 3) * 4;
    int brow = tid >> 4, bcol = (tid & 15) * 4;
    int rowBase = blockIdx.y * BM, colBase = blockIdx.x * BN;
    float acc[4][4] = {};
    for (int k0 = 0; k0 < Hh; k0 += BK) {
        float4 a = *(const float4*)(A + (size_t)(rowBase + arow) * Hh + k0 + acol);
        As[acol+0][arow] = a.x; As[acol+1][arow] = a.y;
        As[acol+2][arow] = a.z; As[acol+3][arow] = a.w;
        *(float4*)&Bs[brow][bcol] =
            *(const float4*)(Bm + (size_t)(k0 + brow) * Hh + colBase + bcol);
        __syncthreads();
        #pragma unroll
        for (int kk = 0; kk < BK; kk++) {
            float4 av = *(float4*)&As[kk][ty * 4];
            float4 bv = *(float4*)&Bs[kk][tx * 4];
            float ar[4] = {av.x, av.y, av.z, av.w};
            float br[4] = {bv.x, bv.y, bv.z, bv.w};
            #pragma unroll
            for (int i = 0; i < 4; i++)
                #pragma unroll
                for (int j = 0; j < 4; j++) acc[i][j] += ar[i] * br[j];
        }
        __syncthreads();
    }
    #pragma unroll
    for (int i = 0; i < 4; i++) {
        float4 o = make_float4(acc[i][0], acc[i][1], acc[i][2], acc[i][3]);
        *(float4*)(C + (size_t)(rowBase + ty * 4 + i) * Hh + colBase + tx * 4) = o;
    }
}

// WO with residual: h = x + ao @ wo
__global__ void k_wo(const float* __restrict__ wo, const float* __restrict__ x) {
    const float* A = g_ao;
    __shared__ float As[BK][BM];
    __shared__ float Bs[BK][BN];
    int tx = threadIdx.x, ty = threadIdx.y;
    int tid = ty * 16 + tx;
    int arow = tid >> 2, acol = (tid & 3) * 4;
    int brow = tid >> 4, bcol = (tid & 15) * 4;
    int rowBase = blockIdx.y * BM, colBase = blockIdx.x * BN;
    float acc[4][4] = {};
    for (int k0 = 0; k0 < Hh; k0 += BK) {
        float4 a = *(const float4*)(A + (size_t)(rowBase + arow) * Hh + k0 + acol);
        As[acol+0][arow] = a.x; As[acol+1][arow] = a.y;
        As[acol+2][arow] = a.z; As[acol+3][arow] = a.w;
        *(float4*)&Bs[brow][bcol] =
            *(const float4*)(wo + (size_t)(k0 + brow) * Hh + colBase + bcol);
        __syncthreads();
        #pragma unroll
        for (int kk = 0; kk < BK; kk++) {
            float4 av = *(float4*)&As[kk][ty * 4];
            float4 bv = *(float4*)&Bs[kk][tx * 4];
            float ar[4] = {av.x, av.y, av.z, av.w};
            float br[4] = {bv.x, bv.y, bv.z, bv.w};
            #pragma unroll
            for (int i = 0; i < 4; i++)
                #pragma unroll
                for (int j = 0; j < 4; j++) acc[i][j] += ar[i] * br[j];
        }
        __syncthreads();
    }
    #pragma unroll
    for (int i = 0; i < 4; i++) {
        size_t ro = (size_t)(rowBase + ty * 4 + i) * Hh + colBase + tx * 4;
        float4 xv = *(const float4*)(x + ro);
        float4 o = make_float4(acc[i][0] + xv.x, acc[i][1] + xv.y,
                               acc[i][2] + xv.z, acc[i][3] + xv.w);
        *(float4*)(g_h + ro) = o;
    }
}

// ---------------- attention: one warp per (b, head, query row) ----------------
__device__ __forceinline__ void attn_update(float s, float vx, float vy,
                                            float& m, float& l, float& ax, float& ay) {
    float mn = fmaxf(m, s);
    float sc = __expf(m - mn);
    float p  = __expf(s - mn);
    l  = l * sc + p;
    ax = ax * sc + p * vx;
    ay = ay * sc + p * vy;
    m  = mn;
}

__global__ void k_attn() {
    int gw   = (blockIdx.x * blockDim.x + threadIdx.x) >> 5;
    int lane = threadIdx.x & 31;
    if (gw >= Bb * NHh * Ss) return;
    int qi   = gw & (Ss - 1);
    int bh   = gw >> 10;
    int head = bh & (NHh - 1);
    int b    = bh >> 4;
    float2 qv = *(const float2*)(g_q + (size_t)(b * Ss + qi) * Hh + head * HDd + 2 * lane);
    qv.x *= 0.125f; qv.y *= 0.125f;          // 1/sqrt(64)
    const float* kb = g_k + ((size_t)b * Ss * Hh + head * HDd + 2 * lane);
    const float* vb = g_v + ((size_t)b * Ss * Hh + head * HDd + 2 * lane);
    float m = -1e30f, l = 0.f, ax = 0.f, ay = 0.f;
    int nk = qi + 1;
    int j = 0;
    for (; j + 4 <= nk; j += 4) {
        float2 k0 = *(const float2*)(kb + (size_t)(j + 0) * Hh);
        float2 k1 = *(const float2*)(kb + (size_t)(j + 1) * Hh);
        float2 k2 = *(const float2*)(kb + (size_t)(j + 2) * Hh);
        float2 k3 = *(const float2*)(kb + (size_t)(j + 3) * Hh);
        float s0 = qv.x * k0.x + qv.y * k0.y;
        float s1 = qv.x * k1.x + qv.y * k1.y;
        float s2 = qv.x * k2.x + qv.y * k2.y;
        float s3 = qv.x * k3.x + qv.y * k3.y;
        #pragma unroll
        for (int o = 16; o > 0; o >>= 1) {
            s0 += __shfl_xor_sync(0xffffffffu, s0, o);
            s1 += __shfl_xor_sync(0xffffffffu, s1, o);
            s2 += __shfl_xor_sync(0xffffffffu, s2, o);
            s3 += __shfl_xor_sync(0xffffffffu, s3, o);
        }
        float2 v0 = *(const float2*)(vb + (size_t)(j + 0) * Hh);
        float2 v1 = *(const float2*)(vb + (size_t)(j + 1) * Hh);
        float2 v2 = *(const float2*)(vb + (size_t)(j + 2) * Hh);
        float2 v3 = *(const float2*)(vb + (size_t)(j + 3) * Hh);
        attn_update(s0, v0.x, v0.y, m, l, ax, ay);
        attn_update(s1, v1.x, v1.y, m, l, ax, ay);
        attn_update(s2, v2.x, v2.y, m, l, ax, ay);
        attn_update(s3, v3.x, v3.y, m, l, ax, ay);
    }
    for (; j < nk; j++) {
        float2 kvv = *(const float2*)(kb + (size_t)j * Hh);
        float s = qv.x * kvv.x + qv.y * kvv.y;
        #pragma unroll
        for (int o = 16; o > 0; o >>= 1) s += __shfl_xor_sync(0xffffffffu, s, o);
        float2 vv = *(const float2*)(vb + (size_t)j * Hh);
        attn_update(s, vv.x, vv.y, m, l, ax, ay);
    }
    float inv = 1.f / l;
    float2 o = make_float2(ax * inv, ay * inv);
    *(float2*)(g_ao + (size_t)(b * Ss + qi) * Hh + head * HDd + 2 * lane) = o;
}

// ---------------- router: one warp per token ----------------
__global__ void k_router(const float* __restrict__ rw) {
    int t    = (blockIdx.x * blockDim.x + threadIdx.x) >> 5;
    int lane = threadIdx.x & 31;
    if (t >= Tt) return;
    const float* xr = g_hn + (size_t)t * Hh;
    float acc[Ee] = {};
    for (int hh = lane; hh < Hh; hh += 32) {
        float xv = xr[hh];
        #pragma unroll
        for (int e = 0; e < Ee; e++) acc[e] += xv * rw[hh * Ee + e];
    }
    #pragma unroll
    for (int e = 0; e < Ee; e++)
        #pragma unroll
        for (int o = 16; o > 0; o >>= 1) acc[e] += __shfl_xor_sync(0xffffffffu, acc[e], o);
    if (lane == 0) {
        float mx = acc[0];
        #pragma unroll
        for (int e = 1; e < Ee; e++) mx = fmaxf(mx, acc[e]);
        float p[Ee], s = 0.f;
        #pragma unroll
        for (int e = 0; e < Ee; e++) { p[e] = __expf(acc[e] - mx); s += p[e]; }
        float invs = 1.f / s;
        #pragma unroll
        for (int e = 0; e < Ee; e++) p[e] *= invs;
        int i1 = 0; float v1 = p[0];
        #pragma unroll
        for (int e = 1; e < Ee; e++) if (p[e] > v1) { v1 = p[e]; i1 = e; }
        int i2 = -1; float v2 = -1.f;
        #pragma unroll
        for (int e = 0; e < Ee; e++) if (e != i1 && p[e] > v2) { v2 = p[e]; i2 = e; }
        float inv = 1.f / (v1 + v2);
        g_topi[t * 2]     = i1; g_topi[t * 2 + 1] = i2;
        g_topw[t * 2]     = v1 * inv; g_topw[t * 2 + 1] = v2 * inv;
        atomicAdd(&g_cnt[i1], 1); atomicAdd(&g_cnt[i2], 1);
    }
}

__global__ void k_scan() {
    if (threadIdx.x == 0) {
        int o = 0;
        for (int e = 0; e < Ee; e++) { g_off[e] = o; o += g_cnt[e]; g_fill[e] = 0; }
    }
}

__global__ void k_fill() {
    int t = blockIdx.x * blockDim.x + threadIdx.x;
    if (t >= Tt) return;
    for (int kk = 0; kk < 2; kk++) {
        int e = g_topi[t * 2 + kk];
        int pos = atomicAdd(&g_fill[e], 1);
        int slot = g_off[e] + pos;
        g_tok[slot] = t;
        g_slot[t * 2 + kk] = slot;
    }
}

// ---------------- MoE GEMM 1: act = silu(hn@w1) * (hn@w3), gathered rows ----------------
__global__ void k_moe1(const float* __restrict__ w1, const float* __restrict__ w3) {
    int e = blockIdx.z;
    int cnt = g_cnt[e], base = g_off[e];
    int rtile = blockIdx.y * BM;
    if (rtile >= cnt) return;
    const float* B1 = w1 + (size_t)e * Hh * Ii;
    const float* B3 = w3 + (size_t)e * Hh * Ii;
    __shared__ float As[BK][BM];
    __shared__ float Bs1[BK][BN];
    __shared__ float Bs3[BK][BN];
    int tx = threadIdx.x, ty = threadIdx.y;
    int tid = ty * 16 + tx;
    int arow = tid >> 2, acol = (tid & 3) * 4;
    int brow = tid >> 4, bcol = (tid & 15) * 4;
    int colBase = blockIdx.x * BN;
    bool validA = (rtile + arow) < cnt;
    int tok = validA ? g_tok[base + rtile + arow] : g_tok[base];
    const float* Aptr = g_hn + (size_t)tok * Hh;
    float acc1[4][4] = {}, acc3[4][4] = {};
    for (int k0 = 0; k0 < Hh; k0 += BK) {
        float4 a = *(const float4*)(Aptr + k0 + acol);
        As[acol+0][arow] = a.x; As[acol+1][arow] = a.y;
        As[acol+2][arow] = a.z; As[acol+3][arow] = a.w;
        *(float4*)&Bs1[brow][bcol] =
            *(const float4*)(B1 + (size_t)(k0 + brow) * Ii + colBase + bcol);
        *(float4*)&Bs3[brow][bcol] =
            *(const float4*)(B3 + (size_t)(k0 + brow) * Ii + colBase + bcol);
        __syncthreads();
        #pragma unroll
        for (int kk = 0; kk < BK; kk++) {
            float4 av = *(float4*)&As[kk][ty * 4];
            float4 b1v = *(float4*)&Bs1[kk][tx * 4];
            float4 b3v = *(float4*)&Bs3[kk][tx * 4];
            float ar[4] = {av.x, av.y, av.z, av.w};
            float b1r[4] = {b1v.x, b1v.y, b1v.z, b1v.w};
            float b3r[4] = {b3v.x, b3v.y, b3v.z, b3v.w};
            #pragma unroll
            for (int i = 0; i < 4; i++)
                #pragma unroll
                for (int j = 0; j < 4; j++) {
                    acc1[i][j] += ar[i] * b1r[j];
                    acc3[i][j] += ar[i] * b3r[j];
                }
        }
        __syncthreads();
    }
    #pragma unroll
    for (int i = 0; i < 4; i++) {
        int rloc = rtile + ty * 4 + i;
        if (rloc >= cnt) continue;
        float4 o;
        float* op = &o.x;
        #pragma unroll
        for (int j = 0; j < 4; j++) {
            float h1 = acc1[i][j], h3 = acc3[i][j];
            op[j] = (h1 / (1.f + __expf(-h1))) * h3;
        }
        *(float4*)(g_act + (size_t)(base + rloc) * Ii + colBase + tx * 4) = o;
    }
}

// ---------------- MoE GEMM 2: y = act @ w2[e] ----------------
__global__ void k_moe2(const float* __restrict__ w2) {
    int e = blockIdx.z;
    int cnt = g_cnt[e], base = g_off[e];
    int rtile = blockIdx.y * BM;
    if (rtile >= cnt) return;
    const float* Bm = w2 + (size_t)e * Ii * Hh;
    __shared__ float As[BK][BM];
    __shared__ float Bs[BK][BN];
    int tx = threadIdx.x, ty = threadIdx.y;
    int tid = ty * 16 + tx;
    int arow = tid >> 2, acol = (tid & 3) * 4;
    int brow = tid >> 4, bcol = (tid & 15) * 4;
    int colBase = blockIdx.x * BN;
    bool validA = (rtile + arow) < cnt;
    int rowIdx = validA ? (base + rtile + arow) : base;
    const float* Aptr = g_act + (size_t)rowIdx * Ii;
    float acc[4][4] = {};
    for (int k0 = 0; k0 < Ii; k0 += BK) {
        float4 a = *(const float4*)(Aptr + k0 + acol);
        As[acol+0][arow] = a.x; As[acol+1][arow] = a.y;
        As[acol+2][arow] = a.z; As[acol+3][arow] = a.w;
        *(float4*)&Bs[brow][bcol] =
            *(const float4*)(Bm + (size_t)(k0 + brow) * Hh + colBase + bcol);
        __syncthreads();
        #pragma unroll
        for (int kk = 0; kk < BK; kk++) {
            float4 av = *(float4*)&As[kk][ty * 4];
            float4 bv = *(float4*)&Bs[kk][tx * 4];
            float ar[4] = {av.x, av.y, av.z, av.w};
            float br[4] = {bv.x, bv.y, bv.z, bv.w};
            #pragma unroll
            for (int i = 0; i < 4; i++)
                #pragma unroll
                for (int j = 0; j < 4; j++) acc[i][j] += ar[i] * br[j];
        }
        __syncthreads();
    }
    #pragma unroll
    for (int i = 0; i < 4; i++) {
        int rloc = rtile + ty * 4 + i;
        if (rloc >= cnt) continue;
        float4 o = make_float4(acc[i][0], acc[i][1], acc[i][2], acc[i][3]);
        *(float4*)(g_y + (size_t)(base + rloc) * Hh + colBase + tx * 4) = o;
    }
}

// ---------------- combine: out = h + w0*y[slot0] + w1*y[slot1] ----------------
__global__ void k_combine(float* __restrict__ out) {
    int t = blockIdx.x;
    int i = threadIdx.x;                 // 256 threads * float4 = 1024
    int s0 = g_slot[t * 2], s1 = g_slot[t * 2 + 1];
    float w0 = g_topw[t * 2], w1 = g_topw[t * 2 + 1];
    float4 hv = ((const float4*)g_h)[(size_t)t * 256 + i];
    float4 y0 = ((const float4*)g_y)[(size_t)s0 * 256 + i];
    float4 y1 = ((const float4*)g_y)[(size_t)s1 * 256 + i];
    float4 o;
    o.x = hv.x + w0 * y0.x + w1 * y1.x;
    o.y = hv.y + w0 * y0.y + w1 * y1.y;
    o.z = hv.z + w0 * y0.z + w1 * y1.z;
    o.w = hv.w + w0 * y0.w + w1 * y1.w;
    ((float4*)out)[(size_t)t * 256 + i] = o;
}

// ---------------- launch ----------------
extern "C" void kernel_launch(void* const* d_in, const int* in_sizes, int n_in,
                              void* d_out, int out_size) {
    const float* x    = (const float*)d_in[0];
    const float* anw  = (const float*)d_in[1];
    const float* fnw  = (const float*)d_in[2];
    const float* wq   = (const float*)d_in[3];
    const float* wk   = (const float*)d_in[4];
    const float* wv   = (const float*)d_in[5];
    const float* wo   = (const float*)d_in[6];
    const float* rw   = (const float*)d_in[7];
    const float* w1   = (const float*)d_in[8];
    const float* w3   = (const float*)d_in[9];
    const float* w2   = (const float*)d_in[10];
    const float* fc   = (const float*)d_in[11];
    float* out = (float*)d_out;

    float* d_xn; cudaGetSymbolAddress((void**)&d_xn, g_xn);
    float* d_h;  cudaGetSymbolAddress((void**)&d_h,  g_h);
    float* d_hn; cudaGetSymbolAddress((void**)&d_hn, g_hn);

    dim3 tb(16, 16);

    k_zero<<<1, 32>>>();
    k_rmsnorm<<<Tt, 256>>>(x, anw, d_xn);
    k_qkv<<<dim3(Hh / BN, Tt / BM, 3), tb>>>(wq, wk, wv);
    k_rope<<<dim3((Tt * NHh * 32) / 256, 2), 256>>>(fc);
    k_attn<<<(Bb * NHh * Ss) / 4, 128>>>();
    k_wo<<<dim3(Hh / BN, Tt / BM), tb>>>(wo, x);
    k_rmsnorm<<<Tt, 256>>>(d_h, fnw, d_hn);
    k_router<<<Tt / 8, 256>>>(rw);
    k_scan<<<1, 32>>>();
    k_fill<<<Tt / 256, 256>>>();
    k_moe1<<<dim3(Ii / BN, Tt / BM, Ee), tb>>>(w1, w3);
    k_moe2<<<dim3(Hh / BN, Tt / BM, Ee), tb>>>(w2);
    k_combine<<<Tt, 256>>>(out);
}

// round 12
// speedup vs baseline: 1.6631x; 1.6553x over previous
#include <cuda_runtime.h>
#include <cuda_bf16.h>
#include <math.h>
#include <stdint.h>

typedef unsigned int u32; typedef unsigned long long u64;
typedef __nv_bfloat16 bf16;

#define Bb   2
#define Ss   1024
#define Tt   2048
#define Hh   1024
#define NHh  16
#define HDd  64
#define Ee   8
#define Ii   2048
#define NSLOT (Tt*2)

// ---- fp32 scratch ----
__device__ float g_xn[Tt*Hh];
__device__ float g_q [Tt*Hh];
__device__ float g_k [Tt*Hh];
__device__ float g_v [Tt*Hh];
__device__ float g_h [Tt*Hh];
__device__ float g_hn[Tt*Hh];
__device__ float g_y [NSLOT*Hh];
__device__ float g_t1[NSLOT*Ii];
__device__ float g_t3[NSLOT*Ii];
__device__ int   g_topi[Tt*2];
__device__ float g_topw[Tt*2];
__device__ int   g_slot[Tt*2];
__device__ int   g_tok [NSLOT];
__device__ int   g_cnt [Ee];
__device__ int   g_off [Ee];
__device__ int   g_fill[Ee];

// ---- bf16 split scratch ----
__device__ __align__(16) bf16 g_xn_hi[Tt*Hh],  g_xn_lo[Tt*Hh];
__device__ __align__(16) bf16 g_hn_hi[Tt*Hh],  g_hn_lo[Tt*Hh];
__device__ __align__(16) bf16 g_ao_hi[Tt*Hh],  g_ao_lo[Tt*Hh];
__device__ __align__(16) bf16 g_act_hi[NSLOT*Ii], g_act_lo[NSLOT*Ii];
__device__ __align__(16) bf16 g_wqkvT_hi[3*Hh*Hh], g_wqkvT_lo[3*Hh*Hh];
__device__ __align__(16) bf16 g_woT_hi[Hh*Hh],     g_woT_lo[Hh*Hh];
__device__ __align__(16) bf16 g_w1T_hi[Ee*Ii*Hh],  g_w1T_lo[Ee*Ii*Hh];
__device__ __align__(16) bf16 g_w3T_hi[Ee*Ii*Hh],  g_w3T_lo[Ee*Ii*Hh];
__device__ __align__(16) bf16 g_w2T_hi[Ee*Hh*Ii],  g_w2T_lo[Ee*Hh*Ii];

// ---------------- low-level helpers (all plain-sm_103-legal) ----------------
__device__ __forceinline__ u32 sm2u(const void* p) {
    u32 a; asm("{ .reg .u64 t; cvta.to.shared.u64 t, %1; cvt.u32.u64 %0, t; }" : "=r"(a) : "l"(p)); return a;
}
__device__ __forceinline__ void cpa16(u32 dst, const void* src) {
    asm volatile("cp.async.cg.shared.global [%0], [%1], 16;" :: "r"(dst), "l"(src));
}
__device__ __forceinline__ void ldmx4(u32& r0, u32& r1, u32& r2, u32& r3, u32 a) {
    asm volatile("ldmatrix.sync.aligned.m8n8.x4.shared.b16 {%0,%1,%2,%3}, [%4];"
        : "=r"(r0), "=r"(r1), "=r"(r2), "=r"(r3) : "r"(a));
}
__device__ __forceinline__ void mma16816(float* c, u32 a0, u32 a1, u32 a2, u32 a3, u32 b0, u32 b1) {
    asm volatile("mma.sync.aligned.m16n8k16.row.col.f32.bf16.bf16.f32 "
        "{%0,%1,%2,%3}, {%4,%5,%6,%7}, {%8,%9}, {%0,%1,%2,%3};"
        : "+f"(c[0]), "+f"(c[1]), "+f"(c[2]), "+f"(c[3])
        : "r"(a0), "r"(a1), "r"(a2), "r"(a3), "r"(b0), "r"(b1));
}

// ---------------- mma.sync GEMM core ----------------
// 128x128 CTA tile, 8 warps (2x4 -> 64x32 warp tiles), BK=64 bf16, SW128 smem,
// double-buffered cp.async. 3-pass split-bf16: AhBh + AhBl + AlBh, fp32 accum.
// SMEM: [Ah, Al, Bh, Bl] x 16KB x 2 stages = 128KB dynamic.
template<bool GATHER>
__device__ __forceinline__ void mma_core(
    const bf16* __restrict__ Ah, const bf16* __restrict__ Al, int ldA, const int* srow,
    const bf16* __restrict__ Bh, const bf16* __restrict__ Bl, int ldB,
    int K, char* sm, float (&acc)[4][4][4])
{
    const int TSZ = 16384, STG = 4 * TSZ;
    int tid = threadIdx.x, wid = tid >> 5, lane = tid & 31;
    u32 smb = sm2u(sm);
    auto load = [&](int c) {
        u32 sb = smb + (c & 1) * STG;
        int k0 = c * 64;
        #pragma unroll
        for (int it = 0; it < 4; it++) {
            int idx = tid + it * 256, row = idx >> 3, seg = idx & 7;
            u32 so = (u32)(row * 128 + ((seg ^ (row & 7)) << 4));
            int ar = GATHER ? srow[row] : row;
            size_t ao = ((size_t)ar * ldA + k0) * 2 + seg * 16;
            cpa16(sb + so,       (const char*)Ah + ao);
            cpa16(sb + TSZ + so, (const char*)Al + ao);
            size_t bo = ((size_t)row * ldB + k0) * 2 + seg * 16;
            cpa16(sb + 2*TSZ + so, (const char*)Bh + bo);
            cpa16(sb + 3*TSZ + so, (const char*)Bl + bo);
        }
        asm volatile("cp.async.commit_group;" ::: "memory");
    };
    int sub = lane >> 3, l7 = lane & 7, segb = sub >> 1;
    int rA = (wid >> 2) * 64 + l7 + (sub & 1) * 8;   // + i*16
    int rB = (wid & 3) * 32 + l7 + (sub & 1) * 8;    // + jj*16
    int NC = K / 64;
    load(0);
    for (int c = 0; c < NC; c++) {
        if (c + 1 < NC) { load(c + 1); asm volatile("cp.async.wait_group 1;" ::: "memory"); }
        else            {              asm volatile("cp.async.wait_group 0;" ::: "memory"); }
        __syncthreads();
        u32 sb = smb + (c & 1) * STG;
        #pragma unroll
        for (int k16 = 0; k16 < 4; k16++) {
            u32 ah[4][4], al[4][4], bh[2][4], bl[2][4];
            #pragma unroll
            for (int i = 0; i < 4; i++) {
                u32 ra = sb + (u32)((rA + i * 16) * 128 + (((k16 * 2 + segb) ^ (rA & 7)) << 4));
                ldmx4(ah[i][0], ah[i][1], ah[i][2], ah[i][3], ra);
                ldmx4(al[i][0], al[i][1], al[i][2], al[i][3], ra + TSZ);
            }
            #pragma unroll
            for (int jj = 0; jj < 2; jj++) {
                u32 rb = sb + (u32)((rB + jj * 16) * 128 + (((k16 * 2 + segb) ^ (rB & 7)) << 4));
                ldmx4(bh[jj][0], bh[jj][1], bh[jj][2], bh[jj][3], rb + 2*TSZ);
                ldmx4(bl[jj][0], bl[jj][1], bl[jj][2], bl[jj][3], rb + 3*TSZ);
            }
            #pragma unroll
            for (int i = 0; i < 4; i++)
                #pragma unroll
                for (int j = 0; j < 4; j++) {
                    int jj = j >> 1, o = j & 1;
                    mma16816(acc[i][j], ah[i][0], ah[i][1], ah[i][2], ah[i][3], bh[jj][o], bh[jj][o+2]);
                    mma16816(acc[i][j], ah[i][0], ah[i][1], ah[i][2], ah[i][3], bl[jj][o], bl[jj][o+2]);
                    mma16816(acc[i][j], al[i][0], al[i][1], al[i][2], al[i][3], bh[jj][o], bh[jj][o+2]);
                }
        }
        __syncthreads();
    }
}

#define SMEMG (4*16384*2)

// ---- GEMM kernels ----
__global__ void __launch_bounds__(256, 1) k_qkv_mm() {
    extern __shared__ char sm[];
    int tid = threadIdx.x, wid = tid >> 5, lane = tid & 31;
    int z = blockIdx.z, rowBase = blockIdx.y * 128, colBase = blockIdx.x * 128;
    float acc[4][4][4] = {};
    mma_core<false>(g_xn_hi + (size_t)rowBase * Hh, g_xn_lo + (size_t)rowBase * Hh, Hh, nullptr,
                    g_wqkvT_hi + ((size_t)z * Hh + colBase) * Hh,
                    g_wqkvT_lo + ((size_t)z * Hh + colBase) * Hh, Hh, Hh, sm, acc);
    float* C = (z == 0) ? g_q : (z == 1) ? g_k : g_v;
    int wR = wid >> 2, wC = wid & 3, lr = lane >> 2, lc = (lane & 3) * 2;
    #pragma unroll
    for (int i = 0; i < 4; i++)
        #pragma unroll
        for (int j = 0; j < 4; j++)
            #pragma unroll
            for (int p = 0; p < 2; p++) {
                int row = wR * 64 + i * 16 + lr + p * 8;
                int col = wC * 32 + j * 8 + lc;
                *(float2*)(C + (size_t)(rowBase + row) * Hh + colBase + col) =
                    make_float2(acc[i][j][2*p], acc[i][j][2*p+1]);
            }
}

__global__ void __launch_bounds__(256, 1) k_wo_mm(const float* __restrict__ x) {
    extern __shared__ char sm[];
    int tid = threadIdx.x, wid = tid >> 5, lane = tid & 31;
    int rowBase = blockIdx.y * 128, colBase = blockIdx.x * 128;
    float acc[4][4][4] = {};
    mma_core<false>(g_ao_hi + (size_t)rowBase * Hh, g_ao_lo + (size_t)rowBase * Hh, Hh, nullptr,
                    g_woT_hi + (size_t)colBase * Hh, g_woT_lo + (size_t)colBase * Hh, Hh, Hh, sm, acc);
    int wR = wid >> 2, wC = wid & 3, lr = lane >> 2, lc = (lane & 3) * 2;
    #pragma unroll
    for (int i = 0; i < 4; i++)
        #pragma unroll
        for (int j = 0; j < 4; j++)
            #pragma unroll
            for (int p = 0; p < 2; p++) {
                int row = wR * 64 + i * 16 + lr + p * 8;
                int col = wC * 32 + j * 8 + lc;
                size_t ro = (size_t)(rowBase + row) * Hh + colBase + col;
                float2 xv = *(const float2*)(x + ro);
                *(float2*)(g_h + ro) = make_float2(acc[i][j][2*p] + xv.x, acc[i][j][2*p+1] + xv.y);
            }
}

__global__ void __launch_bounds__(256, 1) k_h13_mm(const bf16* __restrict__ Wh,
                                                  const bf16* __restrict__ Wl,
                                                  float* __restrict__ out) {
    int e = blockIdx.z, cnt = g_cnt[e], rtile = blockIdx.y * 128;
    if (rtile >= cnt) return;
    extern __shared__ char sm[];
    __shared__ int s_row[128];
    int tid = threadIdx.x, wid = tid >> 5, lane = tid & 31;
    int base = g_off[e], colBase = blockIdx.x * 128;
    if (tid < 128) { int r = rtile + tid; s_row[tid] = g_tok[base + (r < cnt ? r : cnt - 1)]; }
    __syncthreads();
    float acc[4][4][4] = {};
    mma_core<true>(g_hn_hi, g_hn_lo, Hh, s_row,
                   Wh + ((size_t)e * Ii + colBase) * Hh, Wl + ((size_t)e * Ii + colBase) * Hh, Hh,
                   Hh, sm, acc);
    int wR = wid >> 2, wC = wid & 3, lr = lane >> 2, lc = (lane & 3) * 2;
    #pragma unroll
    for (int i = 0; i < 4; i++)
        #pragma unroll
        for (int j = 0; j < 4; j++)
            #pragma unroll
            for (int p = 0; p < 2; p++) {
                int row = wR * 64 + i * 16 + lr + p * 8;
                if (rtile + row < cnt) {
                    int col = wC * 32 + j * 8 + lc;
                    *(float2*)(out + (size_t)(base + rtile + row) * Ii + colBase + col) =
                        make_float2(acc[i][j][2*p], acc[i][j][2*p+1]);
                }
            }
}

__global__ void __launch_bounds__(256, 1) k_moe2_mm() {
    int e = blockIdx.z, cnt = g_cnt[e], rtile = blockIdx.y * 128;
    if (rtile >= cnt) return;
    extern __shared__ char sm[];
    __shared__ int s_row[128];
    int tid = threadIdx.x, wid = tid >> 5, lane = tid & 31;
    int base = g_off[e], colBase = blockIdx.x * 128;
    if (tid < 128) { int r = rtile + tid; s_row[tid] = base + (r < cnt ? r : cnt - 1); }
    __syncthreads();
    float acc[4][4][4] = {};
    mma_core<true>(g_act_hi, g_act_lo, Ii, s_row,
                   g_w2T_hi + ((size_t)e * Hh + colBase) * Ii,
                   g_w2T_lo + ((size_t)e * Hh + colBase) * Ii, Ii, Ii, sm, acc);
    int wR = wid >> 2, wC = wid & 3, lr = lane >> 2, lc = (lane & 3) * 2;
    #pragma unroll
    for (int i = 0; i < 4; i++)
        #pragma unroll
        for (int j = 0; j < 4; j++)
            #pragma unroll
            for (int p = 0; p < 2; p++) {
                int row = wR * 64 + i * 16 + lr + p * 8;
                if (rtile + row < cnt) {
                    int col = wC * 32 + j * 8 + lc;
                    *(float2*)(g_y + (size_t)(base + rtile + row) * Hh + colBase + col) =
                        make_float2(acc[i][j][2*p], acc[i][j][2*p+1]);
                }
            }
}

// ---- transpose + split: in[b][R][C] fp32 -> out[b][C][R] bf16 hi/lo ----
__global__ void k_tsplit(const float* __restrict__ in, bf16* __restrict__ oh,
                         bf16* __restrict__ ol, int R, int C) {
    __shared__ float t[32][33];
    int b = blockIdx.z, c0 = blockIdx.x * 32, r0 = blockIdx.y * 32;
    const float* I = in + (size_t)b * R * C;
    for (int i = threadIdx.y; i < 32; i += 8)
        t[i][threadIdx.x] = I[(size_t)(r0 + i) * C + c0 + threadIdx.x];
    __syncthreads();
    for (int i = threadIdx.y; i < 32; i += 8) {
        float v = t[threadIdx.x][i];
        size_t o = (size_t)b * R * C + (size_t)(c0 + i) * R + r0 + threadIdx.x;
        bf16 h = __float2bfloat16(v);
        oh[o] = h; ol[o] = __float2bfloat16(v - __bfloat162float(h));
    }
}

// ---- elementwise / small kernels ----
__global__ void k_zero() { int i = threadIdx.x; if (i < Ee) { g_cnt[i] = 0; g_fill[i] = 0; } }

__global__ void k_rmsnorm(const float* __restrict__ x, const float* __restrict__ w,
                          float* __restrict__ out, bf16* __restrict__ ohi, bf16* __restrict__ olo) {
    int t = blockIdx.x, i = threadIdx.x;
    float4 v = ((const float4*)(x + (size_t)t * Hh))[i];
    __shared__ float red[256];
    red[i] = v.x*v.x + v.y*v.y + v.z*v.z + v.w*v.w;
    __syncthreads();
    for (int s = 128; s > 0; s >>= 1) { if (i < s) red[i] += red[i+s]; __syncthreads(); }
    float rinv = rsqrtf(red[0] * (1.0f / Hh) + 1e-6f);
    float4 wv = ((const float4*)w)[i];
    float4 o = make_float4(v.x*rinv*wv.x, v.y*rinv*wv.y, v.z*rinv*wv.z, v.w*rinv*wv.w);
    ((float4*)(out + (size_t)t * Hh))[i] = o;
    float ov[4] = {o.x, o.y, o.z, o.w};
    bf16 hh[4], ll[4];
    #pragma unroll
    for (int j = 0; j < 4; j++) {
        hh[j] = __float2bfloat16(ov[j]);
        ll[j] = __float2bfloat16(ov[j] - __bfloat162float(hh[j]));
    }
    *(__nv_bfloat162*)(ohi + (size_t)t*Hh + 4*i)     = __halves2bfloat162(hh[0], hh[1]);
    *(__nv_bfloat162*)(ohi + (size_t)t*Hh + 4*i + 2) = __halves2bfloat162(hh[2], hh[3]);
    *(__nv_bfloat162*)(olo + (size_t)t*Hh + 4*i)     = __halves2bfloat162(ll[0], ll[1]);
    *(__nv_bfloat162*)(olo + (size_t)t*Hh + 4*i + 2) = __halves2bfloat162(ll[2], ll[3]);
}

__global__ void k_rope(const float* __restrict__ fc) {
    int idx = blockIdx.x * blockDim.x + threadIdx.x;
    float* X = (blockIdx.y == 0) ? g_q : g_k;
    int j = idx & 31, head = (idx >> 5) & (NHh - 1), t = idx >> 9;
    if (t >= Tt) return;
    int s = t & (Ss - 1);
    float2* p = (float2*)(X + (size_t)t * Hh + head * HDd + 2*j);
    float2 ab = *p;
    float cr = fc[s * HDd + 2*j], ci = fc[s * HDd + 2*j + 1];
    *p = make_float2(ab.x*cr - ab.y*ci, ab.x*ci + ab.y*cr);
}

__device__ __forceinline__ void attn_update(float s, float vx, float vy,
                                            float& m, float& l, float& ax, float& ay) {
    float mn = fmaxf(m, s), sc = __expf(m - mn), p = __expf(s - mn);
    l = l*sc + p; ax = ax*sc + p*vx; ay = ay*sc + p*vy; m = mn;
}

__global__ void k_attn() {
    int gw = (blockIdx.x * blockDim.x + threadIdx.x) >> 5, lane = threadIdx.x & 31;
    if (gw >= Bb * NHh * Ss) return;
    int qi = gw & (Ss - 1), bh = gw >> 10, head = bh & (NHh - 1), b = bh >> 4;
    float2 qv = *(const float2*)(g_q + (size_t)(b*Ss + qi) * Hh + head*HDd + 2*lane);
    qv.x *= 0.125f; qv.y *= 0.125f;
    const float* kb = g_k + ((size_t)b*Ss*Hh + head*HDd + 2*lane);
    const float* vb = g_v + ((size_t)b*Ss*Hh + head*HDd + 2*lane);
    float m = -1e30f, l = 0.f, ax = 0.f, ay = 0.f;
    int nk = qi + 1, j = 0;
    for (; j + 4 <= nk; j += 4) {
        float2 k0 = *(const float2*)(kb + (size_t)(j+0)*Hh), k1 = *(const float2*)(kb + (size_t)(j+1)*Hh);
        float2 k2 = *(const float2*)(kb + (size_t)(j+2)*Hh), k3 = *(const float2*)(kb + (size_t)(j+3)*Hh);
        float s0 = qv.x*k0.x + qv.y*k0.y, s1 = qv.x*k1.x + qv.y*k1.y;
        float s2 = qv.x*k2.x + qv.y*k2.y, s3 = qv.x*k3.x + qv.y*k3.y;
        #pragma unroll
        for (int o = 16; o > 0; o >>= 1) {
            s0 += __shfl_xor_sync(0xffffffffu, s0, o); s1 += __shfl_xor_sync(0xffffffffu, s1, o);
            s2 += __shfl_xor_sync(0xffffffffu, s2, o); s3 += __shfl_xor_sync(0xffffffffu, s3, o);
        }
        float2 v0 = *(const float2*)(vb + (size_t)(j+0)*Hh), v1 = *(const float2*)(vb + (size_t)(j+1)*Hh);
        float2 v2 = *(const float2*)(vb + (size_t)(j+2)*Hh), v3 = *(const float2*)(vb + (size_t)(j+3)*Hh);
        attn_update(s0, v0.x, v0.y, m, l, ax, ay); attn_update(s1, v1.x, v1.y, m, l, ax, ay);
        attn_update(s2, v2.x, v2.y, m, l, ax, ay); attn_update(s3, v3.x, v3.y, m, l, ax, ay);
    }
    for (; j < nk; j++) {
        float2 kv = *(const float2*)(kb + (size_t)j*Hh);
        float s = qv.x*kv.x + qv.y*kv.y;
        #pragma unroll
        for (int o = 16; o > 0; o >>= 1) s += __shfl_xor_sync(0xffffffffu, s, o);
        float2 vv = *(const float2*)(vb + (size_t)j*Hh);
        attn_update(s, vv.x, vv.y, m, l, ax, ay);
    }
    float inv = 1.f / l;
    float ox = ax*inv, oy = ay*inv;
    size_t oo = (size_t)(b*Ss + qi) * Hh + head*HDd + 2*lane;
    bf16 hx = __float2bfloat16(ox), hy = __float2bfloat16(oy);
    *(__nv_bfloat162*)(g_ao_hi + oo) = __halves2bfloat162(hx, hy);
    *(__nv_bfloat162*)(g_ao_lo + oo) = __halves2bfloat162(
        __float2bfloat16(ox - __bfloat162float(hx)), __float2bfloat16(oy - __bfloat162float(hy)));
}

__global__ void k_router(const float* __restrict__ rw) {
    int t = (blockIdx.x * blockDim.x + threadIdx.x) >> 5, lane = threadIdx.x & 31;
    if (t >= Tt) return;
    const float* xr = g_hn + (size_t)t * Hh;
    float acc[Ee] = {};
    for (int hh = lane; hh < Hh; hh += 32) {
        float xv = xr[hh];
        #pragma unroll
        for (int e = 0; e < Ee; e++) acc[e] += xv * rw[hh * Ee + e];
    }
    #pragma unroll
    for (int e = 0; e < Ee; e++)
        #pragma unroll
        for (int o = 16; o > 0; o >>= 1) acc[e] += __shfl_xor_sync(0xffffffffu, acc[e], o);
    if (lane == 0) {
        float mx = acc[0];
        #pragma unroll
        for (int e = 1; e < Ee; e++) mx = fmaxf(mx, acc[e]);
        float p[Ee], s = 0.f;
        #pragma unroll
        for (int e = 0; e < Ee; e++) { p[e] = __expf(acc[e] - mx); s += p[e]; }
        float invs = 1.f / s;
        #pragma unroll
        for (int e = 0; e < Ee; e++) p[e] *= invs;
        int i1 = 0; float v1 = p[0];
        #pragma unroll
        for (int e = 1; e < Ee; e++) if (p[e] > v1) { v1 = p[e]; i1 = e; }
        int i2 = -1; float v2 = -1.f;
        #pragma unroll
        for (int e = 0; e < Ee; e++) if (e != i1 && p[e] > v2) { v2 = p[e]; i2 = e; }
        float inv = 1.f / (v1 + v2);
        g_topi[t*2] = i1; g_topi[t*2+1] = i2;
        g_topw[t*2] = v1 * inv; g_topw[t*2+1] = v2 * inv;
        atomicAdd(&g_cnt[i1], 1); atomicAdd(&g_cnt[i2], 1);
    }
}

__global__ void k_scan() {
    if (threadIdx.x == 0) {
        int o = 0;
        for (int e = 0; e < Ee; e++) { g_off[e] = o; o += g_cnt[e]; g_fill[e] = 0; }
    }
}

__global__ void k_fill() {
    int t = blockIdx.x * blockDim.x + threadIdx.x;
    if (t >= Tt) return;
    for (int kk = 0; kk < 2; kk++) {
        int e = g_topi[t*2 + kk];
        int slot = g_off[e] + atomicAdd(&g_fill[e], 1);
        g_tok[slot] = t; g_slot[t*2 + kk] = slot;
    }
}

__global__ void k_swiglu() {
    size_t i = (size_t)blockIdx.x * blockDim.x + threadIdx.x;  // bf16 pair index
    float2 h1 = ((const float2*)g_t1)[i];
    float2 h3 = ((const float2*)g_t3)[i];
    float a0 = (h1.x / (1.f + __expf(-h1.x))) * h3.x;
    float a1 = (h1.y / (1.f + __expf(-h1.y))) * h3.y;
    bf16 b0 = __float2bfloat16(a0), b1 = __float2bfloat16(a1);
    ((__nv_bfloat162*)g_act_hi)[i] = __halves2bfloat162(b0, b1);
    ((__nv_bfloat162*)g_act_lo)[i] = __halves2bfloat162(
        __float2bfloat16(a0 - __bfloat162float(b0)), __float2bfloat16(a1 - __bfloat162float(b1)));
}

__global__ void k_combine(float* __restrict__ out) {
    int t = blockIdx.x, i = threadIdx.x;
    int s0 = g_slot[t*2], s1 = g_slot[t*2+1];
    float w0 = g_topw[t*2], w1 = g_topw[t*2+1];
    float4 hv = ((const float4*)g_h)[(size_t)t*256 + i];
    float4 y0 = ((const float4*)g_y)[(size_t)s0*256 + i];
    float4 y1 = ((const float4*)g_y)[(size_t)s1*256 + i];
    ((float4*)out)[(size_t)t*256 + i] = make_float4(
        hv.x + w0*y0.x + w1*y1.x, hv.y + w0*y0.y + w1*y1.y,
        hv.z + w0*y0.z + w1*y1.z, hv.w + w0*y0.w + w1*y1.w);
}

// ---------------- launch ----------------
extern "C" void kernel_launch(void* const* d_in, const int* in_sizes, int n_in,
                              void* d_out, int out_size) {
    const float* x   = (const float*)d_in[0];
    const float* anw = (const float*)d_in[1];
    const float* fnw = (const float*)d_in[2];
    const float* wq  = (const float*)d_in[3];
    const float* wk  = (const float*)d_in[4];
    const float* wv  = (const float*)d_in[5];
    const float* wo  = (const float*)d_in[6];
    const float* rw  = (const float*)d_in[7];
    const float* w1  = (const float*)d_in[8];
    const float* w3  = (const float*)d_in[9];
    const float* w2  = (const float*)d_in[10];
    const float* fc  = (const float*)d_in[11];
    float* out = (float*)d_out;

    static int init = 0;
    if (!init) {
        cudaFuncSetAttribute(k_qkv_mm,  cudaFuncAttributeMaxDynamicSharedMemorySize, SMEMG);
        cudaFuncSetAttribute(k_wo_mm,   cudaFuncAttributeMaxDynamicSharedMemorySize, SMEMG);
        cudaFuncSetAttribute(k_h13_mm,  cudaFuncAttributeMaxDynamicSharedMemorySize, SMEMG);
        cudaFuncSetAttribute(k_moe2_mm, cudaFuncAttributeMaxDynamicSharedMemorySize, SMEMG);
        init = 1;
    }

    float *d_xn, *d_h, *d_hn, *d_t1, *d_t3;
    bf16 *d_xnh, *d_xnl, *d_hnh, *d_hnl;
    bf16 *d_qkvh, *d_qkvl, *d_woh, *d_wol, *d_w1h, *d_w1l, *d_w3h, *d_w3l, *d_w2h, *d_w2l;
    cudaGetSymbolAddress((void**)&d_xn, g_xn);   cudaGetSymbolAddress((void**)&d_h, g_h);
    cudaGetSymbolAddress((void**)&d_hn, g_hn);
    cudaGetSymbolAddress((void**)&d_t1, g_t1);   cudaGetSymbolAddress((void**)&d_t3, g_t3);
    cudaGetSymbolAddress((void**)&d_xnh, g_xn_hi); cudaGetSymbolAddress((void**)&d_xnl, g_xn_lo);
    cudaGetSymbolAddress((void**)&d_hnh, g_hn_hi); cudaGetSymbolAddress((void**)&d_hnl, g_hn_lo);
    cudaGetSymbolAddress((void**)&d_qkvh, g_wqkvT_hi); cudaGetSymbolAddress((void**)&d_qkvl, g_wqkvT_lo);
    cudaGetSymbolAddress((void**)&d_woh, g_woT_hi);    cudaGetSymbolAddress((void**)&d_wol, g_woT_lo);
    cudaGetSymbolAddress((void**)&d_w1h, g_w1T_hi);    cudaGetSymbolAddress((void**)&d_w1l, g_w1T_lo);
    cudaGetSymbolAddress((void**)&d_w3h, g_w3T_hi);    cudaGetSymbolAddress((void**)&d_w3l, g_w3T_lo);
    cudaGetSymbolAddress((void**)&d_w2h, g_w2T_hi);    cudaGetSymbolAddress((void**)&d_w2l, g_w2T_lo);

    dim3 tt(32, 8);
    k_zero<<<1, 32>>>();
    k_tsplit<<<dim3(Hh/32, Hh/32, 1), tt>>>(wq, d_qkvh,           d_qkvl,           Hh, Hh);
    k_tsplit<<<dim3(Hh/32, Hh/32, 1), tt>>>(wk, d_qkvh + Hh*Hh,   d_qkvl + Hh*Hh,   Hh, Hh);
    k_tsplit<<<dim3(Hh/32, Hh/32, 1), tt>>>(wv, d_qkvh + 2*Hh*Hh, d_qkvl + 2*Hh*Hh, Hh, Hh);
    k_tsplit<<<dim3(Hh/32, Hh/32, 1), tt>>>(wo, d_woh, d_wol, Hh, Hh);
    k_tsplit<<<dim3(Ii/32, Hh/32, Ee), tt>>>(w1, d_w1h, d_w1l, Hh, Ii);
    k_tsplit<<<dim3(Ii/32, Hh/32, Ee), tt>>>(w3, d_w3h, d_w3l, Hh, Ii);
    k_tsplit<<<dim3(Hh/32, Ii/32, Ee), tt>>>(w2, d_w2h, d_w2l, Ii, Hh);

    k_rmsnorm<<<Tt, 256>>>(x, anw, d_xn, d_xnh, d_xnl);
    k_qkv_mm<<<dim3(Hh/128, Tt/128, 3), 256, SMEMG>>>();
    k_rope<<<dim3((Tt * NHh * 32) / 256, 2), 256>>>(fc);
    k_attn<<<(Bb * NHh * Ss) / 4, 128>>>();
    k_wo_mm<<<dim3(Hh/128, Tt/128), 256, SMEMG>>>(x);
    k_rmsnorm<<<Tt, 256>>>(d_h, fnw, d_hn, d_hnh, d_hnl);
    k_router<<<Tt / 8, 256>>>(rw);
    k_scan<<<1, 32>>>();
    k_fill<<<Tt / 256, 256>>>();
    k_h13_mm<<<dim3(Ii/128, Tt/128, Ee), 256, SMEMG>>>(d_w1h, d_w1l, d_t1);
    k_h13_mm<<<dim3(Ii/128, Tt/128, Ee), 256, SMEMG>>>(d_w3h, d_w3l, d_t3);
    k_swiglu<<<(NSLOT * Ii / 2) / 256, 256>>>();
    k_moe2_mm<<<dim3(Hh/128, Tt/128, Ee), 256, SMEMG>>>();
    k_combine<<<Tt, 256>>>(out);
}

// round 13
// speedup vs baseline: 1.9052x; 1.1456x over previous
#include <cuda_runtime.h>
#include <cuda_bf16.h>
#include <math.h>
#include <stdint.h>

typedef unsigned int u32; typedef unsigned long long u64;
typedef __nv_bfloat16 bf16;

#define Bb   2
#define Ss   1024
#define Tt   2048
#define Hh   1024
#define NHh  16
#define HDd  64
#define Ee   8
#define Ii   2048
#define NSLOT (Tt*2)

// ---- fp32 scratch ----
__device__ float g_xn[Tt*Hh];
__device__ float g_q [Tt*Hh];
__device__ float g_k [Tt*Hh];
__device__ float g_v [Tt*Hh];
__device__ float g_h [Tt*Hh];
__device__ float g_hn[Tt*Hh];
__device__ float g_y [NSLOT*Hh];
__device__ float g_t1[NSLOT*Ii];
__device__ float g_t3[NSLOT*Ii];
__device__ int   g_topi[Tt*2];
__device__ float g_topw[Tt*2];
__device__ int   g_slot[Tt*2];
__device__ int   g_tok [NSLOT];
__device__ int   g_cnt [Ee];
__device__ int   g_off [Ee];
__device__ int   g_fill[Ee];

// ---- bf16 split scratch (weights stay ROW-MAJOR now; no transpose) ----
__device__ __align__(16) bf16 g_xn_hi[Tt*Hh],  g_xn_lo[Tt*Hh];
__device__ __align__(16) bf16 g_hn_hi[Tt*Hh],  g_hn_lo[Tt*Hh];
__device__ __align__(16) bf16 g_ao_hi[Tt*Hh],  g_ao_lo[Tt*Hh];
__device__ __align__(16) bf16 g_act_hi[NSLOT*Ii], g_act_lo[NSLOT*Ii];
__device__ __align__(16) bf16 g_wqkv_hi[3*Hh*Hh], g_wqkv_lo[3*Hh*Hh];   // [z][H][H]
__device__ __align__(16) bf16 g_wo_hi[Hh*Hh],     g_wo_lo[Hh*Hh];       // [H][H]
__device__ __align__(16) bf16 g_w1_hi[Ee*Hh*Ii],  g_w1_lo[Ee*Hh*Ii];    // [e][H][I]
__device__ __align__(16) bf16 g_w3_hi[Ee*Hh*Ii],  g_w3_lo[Ee*Hh*Ii];    // [e][H][I]
__device__ __align__(16) bf16 g_w2_hi[Ee*Ii*Hh],  g_w2_lo[Ee*Ii*Hh];    // [e][I][H]

// ---------------- low-level helpers (plain-sm_103-legal) ----------------
__device__ __forceinline__ u32 sm2u(const void* p) {
    u32 a; asm("{ .reg .u64 t; cvta.to.shared.u64 t, %1; cvt.u32.u64 %0, t; }" : "=r"(a) : "l"(p)); return a;
}
__device__ __forceinline__ void cpa16(u32 dst, const void* src) {
    asm volatile("cp.async.cg.shared.global [%0], [%1], 16;" :: "r"(dst), "l"(src));
}
__device__ __forceinline__ void ldmx4(u32& r0, u32& r1, u32& r2, u32& r3, u32 a) {
    asm volatile("ldmatrix.sync.aligned.m8n8.x4.shared.b16 {%0,%1,%2,%3}, [%4];"
        : "=r"(r0), "=r"(r1), "=r"(r2), "=r"(r3) : "r"(a));
}
__device__ __forceinline__ void ldmx4t(u32& r0, u32& r1, u32& r2, u32& r3, u32 a) {
    asm volatile("ldmatrix.sync.aligned.m8n8.x4.trans.shared.b16 {%0,%1,%2,%3}, [%4];"
        : "=r"(r0), "=r"(r1), "=r"(r2), "=r"(r3) : "r"(a));
}
__device__ __forceinline__ void mma16816(float* c, u32 a0, u32 a1, u32 a2, u32 a3, u32 b0, u32 b1) {
    asm volatile("mma.sync.aligned.m16n8k16.row.col.f32.bf16.bf16.f32 "
        "{%0,%1,%2,%3}, {%4,%5,%6,%7}, {%8,%9}, {%0,%1,%2,%3};"
        : "+f"(c[0]), "+f"(c[1]), "+f"(c[2]), "+f"(c[3])
        : "r"(a0), "r"(a1), "r"(a2), "r"(a3), "r"(b0), "r"(b1));
}

// ---------------- mma.sync GEMM core ----------------
// 128x128 CTA tile, 8 warps (2x4 -> 64x32 warp tiles), BK=64 bf16.
// A: K-major activations [row][k], SMEM tile 128 rows x 128B (SW128-style swizzle),
//    normal ldmatrix.
// B: ROW-MAJOR weights [k][n], SMEM tile 64 k-rows x 256B, swizzle seg^(k&7),
//    ldmatrix.trans (no host-side transpose needed).
// 3-pass split-bf16: AhBh + AhBl + AlBh, fp32 accum.
// SMEM: [Ah, Al, Bh, Bl] x 16KB x 2 stages = 128KB dynamic.
template<bool GATHER>
__device__ __forceinline__ void mma_core(
    const bf16* __restrict__ Ah, const bf16* __restrict__ Al, int ldA, const int* srow,
    const bf16* __restrict__ Bh, const bf16* __restrict__ Bl, int ldB,   // B pre-offset to colBase
    int K, char* sm, float (&acc)[4][4][4])
{
    const int TSZ = 16384, STG = 4 * TSZ;
    int tid = threadIdx.x, wid = tid >> 5, lane = tid & 31;
    u32 smb = sm2u(sm);
    auto load = [&](int c) {
        u32 sb = smb + (c & 1) * STG;
        int k0 = c * 64;
        #pragma unroll
        for (int it = 0; it < 4; it++) {
            int idx = tid + it * 256;
            // A tile: 128 rows x 8 segs (16B each)
            int ar = idx >> 3, as = idx & 7;
            u32 soA = (u32)(ar * 128 + ((as ^ (ar & 7)) << 4));
            int arow = GATHER ? srow[ar] : ar;
            size_t ao = ((size_t)arow * ldA + k0 + as * 8) * 2;
            cpa16(sb + soA,       (const char*)Ah + ao);
            cpa16(sb + TSZ + soA, (const char*)Al + ao);
            // B tile: 64 k-rows x 16 segs (16B each), row-major source
            int br = idx >> 4, bs = idx & 15;
            u32 soB = (u32)(br * 256 + ((bs ^ (br & 7)) << 4));
            size_t bo = ((size_t)(k0 + br) * ldB + bs * 8) * 2;
            cpa16(sb + 2*TSZ + soB, (const char*)Bh + bo);
            cpa16(sb + 3*TSZ + soB, (const char*)Bl + bo);
        }
        asm volatile("cp.async.commit_group;" ::: "memory");
    };
    int sub = lane >> 3, l7 = lane & 7, segb = sub >> 1;
    int rA = (wid >> 2) * 64 + l7 + (sub & 1) * 8;   // + i*16
    int NC = K / 64;
    load(0);
    for (int c = 0; c < NC; c++) {
        if (c + 1 < NC) { load(c + 1); asm volatile("cp.async.wait_group 1;" ::: "memory"); }
        else            {              asm volatile("cp.async.wait_group 0;" ::: "memory"); }
        __syncthreads();
        u32 sb = smb + (c & 1) * STG;
        #pragma unroll
        for (int k16 = 0; k16 < 4; k16++) {
            u32 ah[4][4], al[4][4], bh[2][4], bl[2][4];
            #pragma unroll
            for (int i = 0; i < 4; i++) {
                u32 ra = sb + (u32)((rA + i * 16) * 128 + (((k16 * 2 + segb) ^ (rA & 7)) << 4));
                ldmx4(ah[i][0], ah[i][1], ah[i][2], ah[i][3], ra);
                ldmx4(al[i][0], al[i][1], al[i][2], al[i][3], ra + TSZ);
            }
            #pragma unroll
            for (int jj = 0; jj < 2; jj++) {
                u32 krow = (u32)(k16 * 16 + (sub & 1) * 8 + l7);
                u32 nseg = (u32)((wid & 3) * 4 + jj * 2 + (sub >> 1));
                u32 rb = sb + krow * 256 + ((nseg ^ (krow & 7)) << 4);
                ldmx4t(bh[jj][0], bh[jj][1], bh[jj][2], bh[jj][3], rb + 2*TSZ);
                ldmx4t(bl[jj][0], bl[jj][1], bl[jj][2], bl[jj][3], rb + 3*TSZ);
            }
            #pragma unroll
            for (int i = 0; i < 4; i++)
                #pragma unroll
                for (int j = 0; j < 4; j++) {
                    int jj = j >> 1, o = (j & 1) * 2;
                    mma16816(acc[i][j], ah[i][0], ah[i][1], ah[i][2], ah[i][3], bh[jj][o], bh[jj][o+1]);
                    mma16816(acc[i][j], ah[i][0], ah[i][1], ah[i][2], ah[i][3], bl[jj][o], bl[jj][o+1]);
                    mma16816(acc[i][j], al[i][0], al[i][1], al[i][2], al[i][3], bh[jj][o], bh[jj][o+1]);
                }
        }
        __syncthreads();
    }
}

#define SMEMG (4*16384*2)

// ---- GEMM kernels ----
__global__ void __launch_bounds__(256, 1) k_qkv_mm() {
    extern __shared__ char sm[];
    int tid = threadIdx.x, wid = tid >> 5, lane = tid & 31;
    int z = blockIdx.z, rowBase = blockIdx.y * 128, colBase = blockIdx.x * 128;
    float acc[4][4][4] = {};
    mma_core<false>(g_xn_hi + (size_t)rowBase * Hh, g_xn_lo + (size_t)rowBase * Hh, Hh, nullptr,
                    g_wqkv_hi + (size_t)z * Hh * Hh + colBase,
                    g_wqkv_lo + (size_t)z * Hh * Hh + colBase, Hh, Hh, sm, acc);
    float* C = (z == 0) ? g_q : (z == 1) ? g_k : g_v;
    int wR = wid >> 2, wC = wid & 3, lr = lane >> 2, lc = (lane & 3) * 2;
    #pragma unroll
    for (int i = 0; i < 4; i++)
        #pragma unroll
        for (int j = 0; j < 4; j++)
            #pragma unroll
            for (int p = 0; p < 2; p++) {
                int row = wR * 64 + i * 16 + lr + p * 8;
                int col = wC * 32 + j * 8 + lc;
                *(float2*)(C + (size_t)(rowBase + row) * Hh + colBase + col) =
                    make_float2(acc[i][j][2*p], acc[i][j][2*p+1]);
            }
}

__global__ void __launch_bounds__(256, 1) k_wo_mm(const float* __restrict__ x) {
    extern __shared__ char sm[];
    int tid = threadIdx.x, wid = tid >> 5, lane = tid & 31;
    int rowBase = blockIdx.y * 128, colBase = blockIdx.x * 128;
    float acc[4][4][4] = {};
    mma_core<false>(g_ao_hi + (size_t)rowBase * Hh, g_ao_lo + (size_t)rowBase * Hh, Hh, nullptr,
                    g_wo_hi + colBase, g_wo_lo + colBase, Hh, Hh, sm, acc);
    int wR = wid >> 2, wC = wid & 3, lr = lane >> 2, lc = (lane & 3) * 2;
    #pragma unroll
    for (int i = 0; i < 4; i++)
        #pragma unroll
        for (int j = 0; j < 4; j++)
            #pragma unroll
            for (int p = 0; p < 2; p++) {
                int row = wR * 64 + i * 16 + lr + p * 8;
                int col = wC * 32 + j * 8 + lc;
                size_t ro = (size_t)(rowBase + row) * Hh + colBase + col;
                float2 xv = *(const float2*)(x + ro);
                *(float2*)(g_h + ro) = make_float2(acc[i][j][2*p] + xv.x, acc[i][j][2*p+1] + xv.y);
            }
}

__global__ void __launch_bounds__(256, 1) k_h13_mm(const bf16* __restrict__ Wh,
                                                  const bf16* __restrict__ Wl,
                                                  float* __restrict__ out) {
    int e = blockIdx.z, cnt = g_cnt[e], rtile = blockIdx.y * 128;
    if (rtile >= cnt) return;
    extern __shared__ char sm[];
    __shared__ int s_row[128];
    int tid = threadIdx.x, wid = tid >> 5, lane = tid & 31;
    int base = g_off[e], colBase = blockIdx.x * 128;
    if (tid < 128) { int r = rtile + tid; s_row[tid] = g_tok[base + (r < cnt ? r : cnt - 1)]; }
    __syncthreads();
    float acc[4][4][4] = {};
    mma_core<true>(g_hn_hi, g_hn_lo, Hh, s_row,
                   Wh + (size_t)e * Hh * Ii + colBase, Wl + (size_t)e * Hh * Ii + colBase, Ii,
                   Hh, sm, acc);
    int wR = wid >> 2, wC = wid & 3, lr = lane >> 2, lc = (lane & 3) * 2;
    #pragma unroll
    for (int i = 0; i < 4; i++)
        #pragma unroll
        for (int j = 0; j < 4; j++)
            #pragma unroll
            for (int p = 0; p < 2; p++) {
                int row = wR * 64 + i * 16 + lr + p * 8;
                if (rtile + row < cnt) {
                    int col = wC * 32 + j * 8 + lc;
                    *(float2*)(out + (size_t)(base + rtile + row) * Ii + colBase + col) =
                        make_float2(acc[i][j][2*p], acc[i][j][2*p+1]);
                }
            }
}

__global__ void __launch_bounds__(256, 1) k_moe2_mm() {
    int e = blockIdx.z, cnt = g_cnt[e], rtile = blockIdx.y * 128;
    if (rtile >= cnt) return;
    extern __shared__ char sm[];
    __shared__ int s_row[128];
    int tid = threadIdx.x, wid = tid >> 5, lane = tid & 31;
    int base = g_off[e], colBase = blockIdx.x * 128;
    if (tid < 128) { int r = rtile + tid; s_row[tid] = base + (r < cnt ? r : cnt - 1); }
    __syncthreads();
    float acc[4][4][4] = {};
    mma_core<true>(g_act_hi, g_act_lo, Ii, s_row,
                   g_w2_hi + (size_t)e * Ii * Hh + colBase,
                   g_w2_lo + (size_t)e * Ii * Hh + colBase, Hh, Ii, sm, acc);
    int wR = wid >> 2, wC = wid & 3, lr = lane >> 2, lc = (lane & 3) * 2;
    #pragma unroll
    for (int i = 0; i < 4; i++)
        #pragma unroll
        for (int j = 0; j < 4; j++)
            #pragma unroll
            for (int p = 0; p < 2; p++) {
                int row = wR * 64 + i * 16 + lr + p * 8;
                if (rtile + row < cnt) {
                    int col = wC * 32 + j * 8 + lc;
                    *(float2*)(g_y + (size_t)(base + rtile + row) * Hh + colBase + col) =
                        make_float2(acc[i][j][2*p], acc[i][j][2*p+1]);
                }
            }
}

// ---- pure elementwise split: fp32 -> bf16 hi/lo (coalesced, no transpose) ----
__global__ void k_split(const float* __restrict__ in, bf16* __restrict__ oh,
                        bf16* __restrict__ ol, int n4) {
    int i = blockIdx.x * blockDim.x + threadIdx.x;
    if (i >= n4) return;
    float4 v = ((const float4*)in)[i];
    float a[4] = {v.x, v.y, v.z, v.w};
    bf16 h[4], l[4];
    #pragma unroll
    for (int j = 0; j < 4; j++) {
        h[j] = __float2bfloat16(a[j]);
        l[j] = __float2bfloat16(a[j] - __bfloat162float(h[j]));
    }
    *(__nv_bfloat162*)(oh + 4*(size_t)i)     = __halves2bfloat162(h[0], h[1]);
    *(__nv_bfloat162*)(oh + 4*(size_t)i + 2) = __halves2bfloat162(h[2], h[3]);
    *(__nv_bfloat162*)(ol + 4*(size_t)i)     = __halves2bfloat162(l[0], l[1]);
    *(__nv_bfloat162*)(ol + 4*(size_t)i + 2) = __halves2bfloat162(l[2], l[3]);
}

// ---- elementwise / small kernels ----
__global__ void k_zero() { int i = threadIdx.x; if (i < Ee) { g_cnt[i] = 0; g_fill[i] = 0; } }

__global__ void k_rmsnorm(const float* __restrict__ x, const float* __restrict__ w,
                          float* __restrict__ out, bf16* __restrict__ ohi, bf16* __restrict__ olo) {
    int t = blockIdx.x, i = threadIdx.x;
    float4 v = ((const float4*)(x + (size_t)t * Hh))[i];
    __shared__ float red[256];
    red[i] = v.x*v.x + v.y*v.y + v.z*v.z + v.w*v.w;
    __syncthreads();
    for (int s = 128; s > 0; s >>= 1) { if (i < s) red[i] += red[i+s]; __syncthreads(); }
    float rinv = rsqrtf(red[0] * (1.0f / Hh) + 1e-6f);
    float4 wv = ((const float4*)w)[i];
    float4 o = make_float4(v.x*rinv*wv.x, v.y*rinv*wv.y, v.z*rinv*wv.z, v.w*rinv*wv.w);
    ((float4*)(out + (size_t)t * Hh))[i] = o;
    float ov[4] = {o.x, o.y, o.z, o.w};
    bf16 hh[4], ll[4];
    #pragma unroll
    for (int j = 0; j < 4; j++) {
        hh[j] = __float2bfloat16(ov[j]);
        ll[j] = __float2bfloat16(ov[j] - __bfloat162float(hh[j]));
    }
    *(__nv_bfloat162*)(ohi + (size_t)t*Hh + 4*i)     = __halves2bfloat162(hh[0], hh[1]);
    *(__nv_bfloat162*)(ohi + (size_t)t*Hh + 4*i + 2) = __halves2bfloat162(hh[2], hh[3]);
    *(__nv_bfloat162*)(olo + (size_t)t*Hh + 4*i)     = __halves2bfloat162(ll[0], ll[1]);
    *(__nv_bfloat162*)(olo + (size_t)t*Hh + 4*i + 2) = __halves2bfloat162(ll[2], ll[3]);
}

__global__ void k_rope(const float* __restrict__ fc) {
    int idx = blockIdx.x * blockDim.x + threadIdx.x;
    float* X = (blockIdx.y == 0) ? g_q : g_k;
    int j = idx & 31, head = (idx >> 5) & (NHh - 1), t = idx >> 9;
    if (t >= Tt) return;
    int s = t & (Ss - 1);
    float2* p = (float2*)(X + (size_t)t * Hh + head * HDd + 2*j);
    float2 ab = *p;
    float cr = fc[s * HDd + 2*j], ci = fc[s * HDd + 2*j + 1];
    *p = make_float2(ab.x*cr - ab.y*ci, ab.x*ci + ab.y*cr);
}

__device__ __forceinline__ void attn_update(float s, float vx, float vy,
                                            float& m, float& l, float& ax, float& ay) {
    float mn = fmaxf(m, s), sc = __expf(m - mn), p = __expf(s - mn);
    l = l*sc + p; ax = ax*sc + p*vx; ay = ay*sc + p*vy; m = mn;
}

__global__ void k_attn() {
    int gw = (blockIdx.x * blockDim.x + threadIdx.x) >> 5, lane = threadIdx.x & 31;
    if (gw >= Bb * NHh * Ss) return;
    int qi = gw & (Ss - 1), bh = gw >> 10, head = bh & (NHh - 1), b = bh >> 4;
    float2 qv = *(const float2*)(g_q + (size_t)(b*Ss + qi) * Hh + head*HDd + 2*lane);
    qv.x *= 0.125f; qv.y *= 0.125f;
    const float* kb = g_k + ((size_t)b*Ss*Hh + head*HDd + 2*lane);
    const float* vb = g_v + ((size_t)b*Ss*Hh + head*HDd + 2*lane);
    float m = -1e30f, l = 0.f, ax = 0.f, ay = 0.f;
    int nk = qi + 1, j = 0;
    for (; j + 4 <= nk; j += 4) {
        float2 k0 = *(const float2*)(kb + (size_t)(j+0)*Hh), k1 = *(const float2*)(kb + (size_t)(j+1)*Hh);
        float2 k2 = *(const float2*)(kb + (size_t)(j+2)*Hh), k3 = *(const float2*)(kb + (size_t)(j+3)*Hh);
        float s0 = qv.x*k0.x + qv.y*k0.y, s1 = qv.x*k1.x + qv.y*k1.y;
        float s2 = qv.x*k2.x + qv.y*k2.y, s3 = qv.x*k3.x + qv.y*k3.y;
        #pragma unroll
        for (int o = 16; o > 0; o >>= 1) {
            s0 += __shfl_xor_sync(0xffffffffu, s0, o); s1 += __shfl_xor_sync(0xffffffffu, s1, o);
            s2 += __shfl_xor_sync(0xffffffffu, s2, o); s3 += __shfl_xor_sync(0xffffffffu, s3, o);
        }
        float2 v0 = *(const float2*)(vb + (size_t)(j+0)*Hh), v1 = *(const float2*)(vb + (size_t)(j+1)*Hh);
        float2 v2 = *(const float2*)(vb + (size_t)(j+2)*Hh), v3 = *(const float2*)(vb + (size_t)(j+3)*Hh);
        attn_update(s0, v0.x, v0.y, m, l, ax, ay); attn_update(s1, v1.x, v1.y, m, l, ax, ay);
        attn_update(s2, v2.x, v2.y, m, l, ax, ay); attn_update(s3, v3.x, v3.y, m, l, ax, ay);
    }
    for (; j < nk; j++) {
        float2 kv = *(const float2*)(kb + (size_t)j*Hh);
        float s = qv.x*kv.x + qv.y*kv.y;
        #pragma unroll
        for (int o = 16; o > 0; o >>= 1) s += __shfl_xor_sync(0xffffffffu, s, o);
        float2 vv = *(const float2*)(vb + (size_t)j*Hh);
        attn_update(s, vv.x, vv.y, m, l, ax, ay);
    }
    float inv = 1.f / l;
    float ox = ax*inv, oy = ay*inv;
    size_t oo = (size_t)(b*Ss + qi) * Hh + head*HDd + 2*lane;
    bf16 hx = __float2bfloat16(ox), hy = __float2bfloat16(oy);
    *(__nv_bfloat162*)(g_ao_hi + oo) = __halves2bfloat162(hx, hy);
    *(__nv_bfloat162*)(g_ao_lo + oo) = __halves2bfloat162(
        __float2bfloat16(ox - __bfloat162float(hx)), __float2bfloat16(oy - __bfloat162float(hy)));
}

__global__ void k_router(const float* __restrict__ rw) {
    int t = (blockIdx.x * blockDim.x + threadIdx.x) >> 5, lane = threadIdx.x & 31;
    if (t >= Tt) return;
    const float* xr = g_hn + (size_t)t * Hh;
    float acc[Ee] = {};
    for (int hh = lane; hh < Hh; hh += 32) {
        float xv = xr[hh];
        #pragma unroll
        for (int e = 0; e < Ee; e++) acc[e] += xv * rw[hh * Ee + e];
    }
    #pragma unroll
    for (int e = 0; e < Ee; e++)
        #pragma unroll
        for (int o = 16; o > 0; o >>= 1) acc[e] += __shfl_xor_sync(0xffffffffu, acc[e], o);
    if (lane == 0) {
        float mx = acc[0];
        #pragma unroll
        for (int e = 1; e < Ee; e++) mx = fmaxf(mx, acc[e]);
        float p[Ee], s = 0.f;
        #pragma unroll
        for (int e = 0; e < Ee; e++) { p[e] = __expf(acc[e] - mx); s += p[e]; }
        float invs = 1.f / s;
        #pragma unroll
        for (int e = 0; e < Ee; e++) p[e] *= invs;
        int i1 = 0; float v1 = p[0];
        #pragma unroll
        for (int e = 1; e < Ee; e++) if (p[e] > v1) { v1 = p[e]; i1 = e; }
        int i2 = -1; float v2 = -1.f;
        #pragma unroll
        for (int e = 0; e < Ee; e++) if (e != i1 && p[e] > v2) { v2 = p[e]; i2 = e; }
        float inv = 1.f / (v1 + v2);
        g_topi[t*2] = i1; g_topi[t*2+1] = i2;
        g_topw[t*2] = v1 * inv; g_topw[t*2+1] = v2 * inv;
        atomicAdd(&g_cnt[i1], 1); atomicAdd(&g_cnt[i2], 1);
    }
}

__global__ void k_scan() {
    if (threadIdx.x == 0) {
        int o = 0;
        for (int e = 0; e < Ee; e++) { g_off[e] = o; o += g_cnt[e]; g_fill[e] = 0; }
    }
}

__global__ void k_fill() {
    int t = blockIdx.x * blockDim.x + threadIdx.x;
    if (t >= Tt) return;
    for (int kk = 0; kk < 2; kk++) {
        int e = g_topi[t*2 + kk];
        int slot = g_off[e] + atomicAdd(&g_fill[e], 1);
        g_tok[slot] = t; g_slot[t*2 + kk] = slot;
    }
}

__global__ void k_swiglu() {
    size_t i = (size_t)blockIdx.x * blockDim.x + threadIdx.x;
    float2 h1 = ((const float2*)g_t1)[i];
    float2 h3 = ((const float2*)g_t3)[i];
    float a0 = (h1.x / (1.f + __expf(-h1.x))) * h3.x;
    float a1 = (h1.y / (1.f + __expf(-h1.y))) * h3.y;
    bf16 b0 = __float2bfloat16(a0), b1 = __float2bfloat16(a1);
    ((__nv_bfloat162*)g_act_hi)[i] = __halves2bfloat162(b0, b1);
    ((__nv_bfloat162*)g_act_lo)[i] = __halves2bfloat162(
        __float2bfloat16(a0 - __bfloat162float(b0)), __float2bfloat16(a1 - __bfloat162float(b1)));
}

__global__ void k_combine(float* __restrict__ out) {
    int t = blockIdx.x, i = threadIdx.x;
    int s0 = g_slot[t*2], s1 = g_slot[t*2+1];
    float w0 = g_topw[t*2], w1 = g_topw[t*2+1];
    float4 hv = ((const float4*)g_h)[(size_t)t*256 + i];
    float4 y0 = ((const float4*)g_y)[(size_t)s0*256 + i];
    float4 y1 = ((const float4*)g_y)[(size_t)s1*256 + i];
    ((float4*)out)[(size_t)t*256 + i] = make_float4(
        hv.x + w0*y0.x + w1*y1.x, hv.y + w0*y0.y + w1*y1.y,
        hv.z + w0*y0.z + w1*y1.z, hv.w + w0*y0.w + w1*y1.w);
}

// ---------------- launch ----------------
extern "C" void kernel_launch(void* const* d_in, const int* in_sizes, int n_in,
                              void* d_out, int out_size) {
    const float* x   = (const float*)d_in[0];
    const float* anw = (const float*)d_in[1];
    const float* fnw = (const float*)d_in[2];
    const float* wq  = (const float*)d_in[3];
    const float* wk  = (const float*)d_in[4];
    const float* wv  = (const float*)d_in[5];
    const float* wo  = (const float*)d_in[6];
    const float* rw  = (const float*)d_in[7];
    const float* w1  = (const float*)d_in[8];
    const float* w3  = (const float*)d_in[9];
    const float* w2  = (const float*)d_in[10];
    const float* fc  = (const float*)d_in[11];
    float* out = (float*)d_out;

    static int init = 0;
    if (!init) {
        cudaFuncSetAttribute(k_qkv_mm,  cudaFuncAttributeMaxDynamicSharedMemorySize, SMEMG);
        cudaFuncSetAttribute(k_wo_mm,   cudaFuncAttributeMaxDynamicSharedMemorySize, SMEMG);
        cudaFuncSetAttribute(k_h13_mm,  cudaFuncAttributeMaxDynamicSharedMemorySize, SMEMG);
        cudaFuncSetAttribute(k_moe2_mm, cudaFuncAttributeMaxDynamicSharedMemorySize, SMEMG);
        init = 1;
    }

    float *d_xn, *d_h, *d_hn, *d_t1, *d_t3;
    bf16 *d_xnh, *d_xnl, *d_hnh, *d_hnl;
    bf16 *d_qkvh, *d_qkvl, *d_woh, *d_wol, *d_w1h, *d_w1l, *d_w3h, *d_w3l, *d_w2h, *d_w2l;
    cudaGetSymbolAddress((void**)&d_xn, g_xn);   cudaGetSymbolAddress((void**)&d_h, g_h);
    cudaGetSymbolAddress((void**)&d_hn, g_hn);
    cudaGetSymbolAddress((void**)&d_t1, g_t1);   cudaGetSymbolAddress((void**)&d_t3, g_t3);
    cudaGetSymbolAddress((void**)&d_xnh, g_xn_hi); cudaGetSymbolAddress((void**)&d_xnl, g_xn_lo);
    cudaGetSymbolAddress((void**)&d_hnh, g_hn_hi); cudaGetSymbolAddress((void**)&d_hnl, g_hn_lo);
    cudaGetSymbolAddress((void**)&d_qkvh, g_wqkv_hi); cudaGetSymbolAddress((void**)&d_qkvl, g_wqkv_lo);
    cudaGetSymbolAddress((void**)&d_woh, g_wo_hi);    cudaGetSymbolAddress((void**)&d_wol, g_wo_lo);
    cudaGetSymbolAddress((void**)&d_w1h, g_w1_hi);    cudaGetSymbolAddress((void**)&d_w1l, g_w1_lo);
    cudaGetSymbolAddress((void**)&d_w3h, g_w3_hi);    cudaGetSymbolAddress((void**)&d_w3l, g_w3_lo);
    cudaGetSymbolAddress((void**)&d_w2h, g_w2_hi);    cudaGetSymbolAddress((void**)&d_w2l, g_w2_lo);

    k_zero<<<1, 32>>>();
    // pure splits (no transpose): fully coalesced
    k_split<<<(Hh*Hh/4)/256, 256>>>(wq, d_qkvh,           d_qkvl,           Hh*Hh/4);
    k_split<<<(Hh*Hh/4)/256, 256>>>(wk, d_qkvh + Hh*Hh,   d_qkvl + Hh*Hh,   Hh*Hh/4);
    k_split<<<(Hh*Hh/4)/256, 256>>>(wv, d_qkvh + 2*Hh*Hh, d_qkvl + 2*Hh*Hh, Hh*Hh/4);
    k_split<<<(Hh*Hh/4)/256, 256>>>(wo, d_woh, d_wol, Hh*Hh/4);
    k_split<<<(Ee*Hh*Ii/4)/256, 256>>>(w1, d_w1h, d_w1l, Ee*Hh*Ii/4);
    k_split<<<(Ee*Hh*Ii/4)/256, 256>>>(w3, d_w3h, d_w3l, Ee*Hh*Ii/4);
    k_split<<<(Ee*Ii*Hh/4)/256, 256>>>(w2, d_w2h, d_w2l, Ee*Ii*Hh/4);

    k_rmsnorm<<<Tt, 256>>>(x, anw, d_xn, d_xnh, d_xnl);
    k_qkv_mm<<<dim3(Hh/128, Tt/128, 3), 256, SMEMG>>>();
    k_rope<<<dim3((Tt * NHh * 32) / 256, 2), 256>>>(fc);
    k_attn<<<(Bb * NHh * Ss) / 4, 128>>>();
    k_wo_mm<<<dim3(Hh/128, Tt/128), 256, SMEMG>>>(x);
    k_rmsnorm<<<Tt, 256>>>(d_h, fnw, d_hn, d_hnh, d_hnl);
    k_router<<<Tt / 8, 256>>>(rw);
    k_scan<<<1, 32>>>();
    k_fill<<<Tt / 256, 256>>>();
    k_h13_mm<<<dim3(Ii/128, Tt/128, Ee), 256, SMEMG>>>(d_w1h, d_w1l, d_t1);
    k_h13_mm<<<dim3(Ii/128, Tt/128, Ee), 256, SMEMG>>>(d_w3h, d_w3l, d_t3);
    k_swiglu<<<(NSLOT * Ii / 2) / 256, 256>>>();
    k_moe2_mm<<<dim3(Hh/128, Tt/128, Ee), 256, SMEMG>>>();
    k_combine<<<Tt, 256>>>(out);
}